// round 2
// baseline (speedup 1.0000x reference)
#include <cuda_runtime.h>
#include <cuda_bf16.h>
#include <cstdint>

#define NB   4
#define TT   2048
#define LL   2048
#define DV   64
#define DQIN 32
#define DF   34
#define ROWS (3 * NB * TT)      // 24576
#define KSPLIT 4
#define CHUNK  (LL / KSPLIT)    // 512
#define KT   128                // keys staged per smem tile
#define TQ   128                // queries per block
#define LOG2E 1.4426950408889634f

// Scratch (device globals; no allocation allowed)
__device__ float g_V[3 * NB * LL * DV];          // 6 MB
__device__ float g_x[3 * NB * LL];
__device__ float g_alpha[ROWS];
__device__ float g_beta[ROWS];
__device__ int   g_cut[ROWS];
__device__ float g_M[ROWS];                      // softmax shift (0 unless cut==LL)
__device__ float g_wa[3 * DQIN];
__device__ float g_wb[3 * DQIN];
__device__ float g_ca[3];
__device__ float g_cb[3];
__device__ float g_invtau[3];
__device__ float g_part[(size_t)KSPLIT * ROWS * DV];  // 25.2 MB partial numerators
__device__ float g_pden[KSPLIT * ROWS];               // partial denominators

typedef unsigned long long ull;

__device__ __forceinline__ void fma2(ull& d, ull a, ull b) {
    asm("fma.rn.f32x2 %0, %1, %2, %0;" : "+l"(d) : "l"(a), "l"(b));
}
__device__ __forceinline__ ull pack2(float x, float y) {
    ull r; asm("mov.b64 %0, {%1, %2};" : "=l"(r) : "f"(x), "f"(y)); return r;
}
__device__ __forceinline__ float ex2(float x) {
    float r; asm("ex2.approx.f32 %0, %1;" : "=f"(r) : "f"(x)); return r;
}

// ---------------------------------------------------------------------------
// prep0: collapse K-path weights.  Q.K = alpha + beta * x  with
//   alpha = ref . wa + ca,  beta = ref . wb + cb
// ---------------------------------------------------------------------------
__global__ void prep0(const float* __restrict__ Wq,
                      const float* __restrict__ Wk1, const float* __restrict__ bk1, const float* __restrict__ lt1,
                      const float* __restrict__ Wk2, const float* __restrict__ bk2, const float* __restrict__ lt2,
                      const float* __restrict__ Wk3, const float* __restrict__ bk3, const float* __restrict__ lt3)
{
    int tid = threadIdx.x;
    const float* Wk[3] = {Wk1, Wk2, Wk3};
    const float* bk[3] = {bk1, bk2, bk3};
    const float* lt[3] = {lt1, lt2, lt3};
    if (tid < 96) {
        int m = tid >> 5, d = tid & 31;
        float sa = Wq[d * 64 + 0];
        float sb = 0.f;
        #pragma unroll 1
        for (int j = 1; j < 64; j++) {
            float w = Wq[d * 64 + j];
            sa -= w * bk[m][j - 1];
            sb -= w * Wk[m][j - 1];
        }
        g_wa[m * DQIN + d] = sa;
        g_wb[m * DQIN + d] = sb;
        if (d == 0) {
            g_ca[m] = -bk[m][63];
            g_cb[m] = -Wk[m][63];
            g_invtau[m] = __expf(-lt[m][0]);
        }
    }
}

// ---------------------------------------------------------------------------
// prep2: V = data[:, :32] @ Wv + bv ; gather x = data[:, 33]
// ---------------------------------------------------------------------------
__global__ void prep2(const float* __restrict__ d1, const float* __restrict__ d2, const float* __restrict__ d3,
                      const float* __restrict__ Wv1, const float* __restrict__ bv1,
                      const float* __restrict__ Wv2, const float* __restrict__ bv2,
                      const float* __restrict__ Wv3, const float* __restrict__ bv3)
{
    int idx = blockIdx.x * blockDim.x + threadIdx.x;
    if (idx >= 3 * NB * LL * DV) return;
    int j   = idx & (DV - 1);
    int row = idx >> 6;                 // m*NB*LL + n*LL + l
    int m   = row / (NB * LL);
    int r   = row - m * (NB * LL);

    const float* data = (m == 0 ? d1 : (m == 1 ? d2 : d3)) + (size_t)r * DF;
    const float* Wv   = (m == 0 ? Wv1 : (m == 1 ? Wv2 : Wv3));
    const float* bv   = (m == 0 ? bv1 : (m == 1 ? bv2 : bv3));

    float s = bv[j];
    #pragma unroll
    for (int i = 0; i < DQIN; i++)
        s = fmaf(data[i], Wv[i * 64 + j], s);
    g_V[idx] = s;
    if (j == 0) g_x[row] = data[33];
}

// ---------------------------------------------------------------------------
// prep1: per (m,n,t) alpha/beta, mask cutoff, and softmax shift M.
// Runs AFTER prep2 (needs g_x for the rare cut==LL max-scan).
// ---------------------------------------------------------------------------
__global__ void prep1(const float* __restrict__ ref_data, const float* __restrict__ ref_t,
                      const float* __restrict__ t1, const float* __restrict__ t2,
                      const float* __restrict__ t3)
{
    int idx = blockIdx.x * blockDim.x + threadIdx.x;  // m*NB*TT + n*TT + t
    if (idx >= ROWS) return;
    int m = idx / (NB * TT);
    int r = idx - m * (NB * TT);
    int n = r / TT;
    int t = r - n * TT;

    const float* rd = ref_data + (size_t)(n * TT + t) * DQIN;
    float a = g_ca[m], b = g_cb[m];
    #pragma unroll
    for (int d = 0; d < DQIN; d++) {
        float v = rd[d];
        a = fmaf(v, g_wa[m * DQIN + d], a);
        b = fmaf(v, g_wb[m * DQIN + d], b);
    }
    g_alpha[idx] = a;
    g_beta[idx]  = b;

    const float* tl = (m == 0 ? t1 : (m == 1 ? t2 : t3)) + (size_t)n * LL;
    float rt = ref_t[n * TT + t];
    int lo = 0, hi = LL;
    while (lo < hi) {
        int mid = (lo + hi) >> 1;
        if (tl[mid] <= rt) lo = mid + 1; else hi = mid;
    }
    g_cut[idx] = lo;

    // softmax shift: 0 unless ALL keys unmasked (then true row max needed)
    float M = 0.f;
    if (lo == LL) {
        const float* xg = g_x + (size_t)(m * NB + n) * LL;
        float minz2 = 3.4e38f;
        #pragma unroll 4
        for (int l = 0; l < LL; l++) {
            float z = fmaf(b, xg[l], a);
            minz2 = fminf(minz2, z * z);
        }
        M = -minz2 * g_invtau[m];
    }
    g_M[idx] = M;
}

// ---------------------------------------------------------------------------
// attn: split-K partial attention.
//   block = (tile of 128 queries) x (key chunk of 512), 128 threads.
//   thread = 4 queries x 16 V-dims  -> each smem V float4 reused 4x,
//   A.V accumulation in packed fma.rn.f32x2.
// Writes partial numerators + denominators; combine() normalizes.
// ---------------------------------------------------------------------------
__global__ __launch_bounds__(128, 4)
void attn()
{
    __shared__ float  xs[KT];
    __shared__ float4 Vs[KT * 16];   // 32 KB
    __shared__ int    sred[4];

    const int bx   = blockIdx.x;          // 0..63
    const int csp  = bx & (KSPLIT - 1);   // key split
    const int tile = bx >> 2;             // query tile (0..15)
    const int n    = blockIdx.y;
    const int m    = blockIdx.z;
    const int tid  = threadIdx.x;
    const int qg   = tid >> 2;            // 0..31
    const int dg   = tid & 3;             // dim group: 16 floats each

    const int rowbase = (m * NB + n) * TT;
    const int t0      = tile * TQ + qg * 4;
    const int cstart  = csp * CHUNK;
    const int cend    = cstart + CHUNK;

    const float c1 = -g_invtau[m] * LOG2E;

    float a[4], b[4], c2[4];
    int   lim[4];
    int   tmax = 0;
    #pragma unroll
    for (int j = 0; j < 4; j++) {
        int rr = rowbase + t0 + j;
        a[j] = g_alpha[rr];
        b[j] = g_beta[rr];
        c2[j] = -g_M[rr] * LOG2E;
        lim[j] = min(g_cut[rr], cend);
        tmax = max(tmax, lim[j]);
    }
    int wmax = __reduce_max_sync(0xffffffffu, tmax);
    if ((tid & 31) == 0) sred[tid >> 5] = wmax;
    __syncthreads();
    const int bend = max(max(sred[0], sred[1]), max(sred[2], sred[3]));

    ull acc[4][8];
    #pragma unroll
    for (int j = 0; j < 4; j++)
        #pragma unroll
        for (int i = 0; i < 8; i++) acc[j][i] = 0ull;
    float den[4] = {0.f, 0.f, 0.f, 0.f};

    const float*  xg  = g_x + (size_t)(m * NB + n) * LL;
    const float4* Vg4 = (const float4*)(g_V + (size_t)(m * NB + n) * LL * DV);

    for (int base = cstart; base < bend; base += KT) {
        xs[tid] = xg[base + tid];
        #pragma unroll
        for (int i = 0; i < 16; i++)
            Vs[tid + i * 128] = Vg4[base * 16 + tid + i * 128];
        __syncthreads();

        int l[4], lmin = KT, lmax = 0;
        #pragma unroll
        for (int j = 0; j < 4; j++) {
            l[j] = min(max(lim[j] - base, 0), KT);
            lmin = min(lmin, l[j]);
            lmax = max(lmax, l[j]);
        }

        // unchecked body: all 4 queries valid
        for (int k = 0; k < lmin; k++) {
            float x = xs[k];
            ull e2[4];
            #pragma unroll
            for (int j = 0; j < 4; j++) {
                float z = fmaf(b[j], x, a[j]);
                float e = ex2(fmaf(z * z, c1, c2[j]));
                den[j] += e;
                e2[j] = pack2(e, e);
            }
            const ulonglong2* vp = (const ulonglong2*)&Vs[k * 16 + dg * 4];
            #pragma unroll
            for (int i = 0; i < 4; i++) {
                ulonglong2 v = vp[i];
                #pragma unroll
                for (int j = 0; j < 4; j++) {
                    fma2(acc[j][2 * i],     e2[j], v.x);
                    fma2(acc[j][2 * i + 1], e2[j], v.y);
                }
            }
        }
        // checked tail: per-query mask boundary
        for (int k = lmin; k < lmax; k++) {
            float x = xs[k];
            ull e2[4];
            #pragma unroll
            for (int j = 0; j < 4; j++) {
                float z = fmaf(b[j], x, a[j]);
                float e = ex2(fmaf(z * z, c1, c2[j]));
                e = (k < l[j]) ? e : 0.f;
                den[j] += e;
                e2[j] = pack2(e, e);
            }
            const ulonglong2* vp = (const ulonglong2*)&Vs[k * 16 + dg * 4];
            #pragma unroll
            for (int i = 0; i < 4; i++) {
                ulonglong2 v = vp[i];
                #pragma unroll
                for (int j = 0; j < 4; j++) {
                    fma2(acc[j][2 * i],     e2[j], v.x);
                    fma2(acc[j][2 * i + 1], e2[j], v.y);
                }
            }
        }
        __syncthreads();
    }

    // write partials (always, including empty blocks -> zeros; deterministic)
    if (dg == 0) {
        float* pp = g_pden + (size_t)csp * ROWS + rowbase + t0;
        #pragma unroll
        for (int j = 0; j < 4; j++) pp[j] = den[j];
    }
    #pragma unroll
    for (int j = 0; j < 4; j++) {
        float4* op = (float4*)(g_part + (((size_t)csp * ROWS + rowbase + t0 + j) << 6) + dg * 16);
        #pragma unroll
        for (int i = 0; i < 4; i++) {
            float2 p0 = *(float2*)&acc[j][2 * i];
            float2 p1 = *(float2*)&acc[j][2 * i + 1];
            op[i] = make_float4(p0.x, p0.y, p1.x, p1.y);
        }
    }
}

// ---------------------------------------------------------------------------
// combine: out[row][:] = (sum_c part[c][row][:]) / (sum_c pden[c][row] + (LL-cut))
// (the (LL-cut)*exp(-M) masked term: M != 0 only when cut==LL, where the
//  term is zero anyway -> plain (LL-cut))
// ---------------------------------------------------------------------------
__global__ void combine(float* __restrict__ out)
{
    int idx = blockIdx.x * blockDim.x + threadIdx.x;   // ROWS * 16 float4s
    if (idx >= ROWS * 16) return;
    int row = idx >> 4;
    int f   = idx & 15;

    float4 s = make_float4(0.f, 0.f, 0.f, 0.f);
    float den = (float)(LL - g_cut[row]);
    #pragma unroll
    for (int c = 0; c < KSPLIT; c++) {
        const float4* p = (const float4*)(g_part + (((size_t)c * ROWS + row) << 6));
        float4 v = p[f];
        s.x += v.x; s.y += v.y; s.z += v.z; s.w += v.w;
        den += g_pden[c * ROWS + row];
    }
    float inv = 1.f / den;
    ((float4*)out)[idx] = make_float4(s.x * inv, s.y * inv, s.z * inv, s.w * inv);
}

// ---------------------------------------------------------------------------
extern "C" void kernel_launch(void* const* d_in, const int* in_sizes, int n_in,
                              void* d_out, int out_size)
{
    const float* ref_data = (const float*)d_in[0];
    const float* ref_t    = (const float*)d_in[1];
    const float* m1_data  = (const float*)d_in[2];
    const float* m1_t     = (const float*)d_in[3];
    const float* m2_data  = (const float*)d_in[4];
    const float* m2_t     = (const float*)d_in[5];
    const float* m3_data  = (const float*)d_in[6];
    const float* m3_t     = (const float*)d_in[7];
    const float* Wq       = (const float*)d_in[8];
    const float* Wk1      = (const float*)d_in[9];
    const float* bk1      = (const float*)d_in[10];
    const float* Wv1      = (const float*)d_in[11];
    const float* bv1      = (const float*)d_in[12];
    const float* lt1      = (const float*)d_in[13];
    const float* Wk2      = (const float*)d_in[14];
    const float* bk2      = (const float*)d_in[15];
    const float* Wv2      = (const float*)d_in[16];
    const float* bv2      = (const float*)d_in[17];
    const float* lt2      = (const float*)d_in[18];
    const float* Wk3      = (const float*)d_in[19];
    const float* bk3      = (const float*)d_in[20];
    const float* Wv3      = (const float*)d_in[21];
    const float* bv3      = (const float*)d_in[22];
    const float* lt3      = (const float*)d_in[23];

    prep0<<<1, 128>>>(Wq, Wk1, bk1, lt1, Wk2, bk2, lt2, Wk3, bk3, lt3);
    prep2<<<(3 * NB * LL * DV) / 256, 256>>>(m1_data, m2_data, m3_data,
                                             Wv1, bv1, Wv2, bv2, Wv3, bv3);
    prep1<<<(ROWS + 127) / 128, 128>>>(ref_data, ref_t, m1_t, m2_t, m3_t);
    attn<<<dim3(16 * KSPLIT, NB, 3), 128>>>();
    combine<<<(ROWS * 16 + 255) / 256, 256>>>((float*)d_out);
}

// round 5
// speedup vs baseline: 1.4854x; 1.4854x over previous
#include <cuda_runtime.h>
#include <cuda_bf16.h>
#include <cstdint>

#define NB   4
#define TT   2048
#define LL   2048
#define DV   64
#define DQIN 32
#define DF   34
#define ROWS (3 * NB * TT)      // 24576
#define KSPLIT 2
#define CHUNK  (LL / KSPLIT)    // 1024
#define KT   64                 // keys per smem tile
#define TQ   64                 // queries per block
#define LOG2E 1.4426950408889634f

// Scratch (device globals; no allocation allowed)
__device__ float g_V[3 * NB * LL * DV];          // 6 MB
__device__ float g_x[3 * NB * LL];
__device__ float g_alpha[ROWS];
__device__ float g_beta[ROWS];
__device__ int   g_cut[ROWS];
__device__ float g_M[ROWS];                      // softmax shift (0 unless cut==LL)
__device__ float g_wa[3 * DQIN];
__device__ float g_wb[3 * DQIN];
__device__ float g_ca[3];
__device__ float g_cb[3];
__device__ float g_invtau[3];
__device__ float g_part[(size_t)KSPLIT * ROWS * DV];  // 12.6 MB partial numerators
__device__ float g_pden[KSPLIT * ROWS];               // partial denominators

typedef unsigned long long ull;

__device__ __forceinline__ void fma2(ull& d, ull a, ull b) {
    asm("fma.rn.f32x2 %0, %1, %2, %0;" : "+l"(d) : "l"(a), "l"(b));
}
__device__ __forceinline__ ull pack2(float x) {
    ull r; asm("mov.b64 %0, {%1, %1};" : "=l"(r) : "f"(x)); return r;
}
__device__ __forceinline__ float ex2(float x) {
    float r; asm("ex2.approx.f32 %0, %1;" : "=f"(r) : "f"(x)); return r;
}

// ---------------------------------------------------------------------------
// prep0: collapse K-path weights.  Q.K = alpha + beta * x
// ---------------------------------------------------------------------------
__global__ void prep0(const float* __restrict__ Wq,
                      const float* __restrict__ Wk1, const float* __restrict__ bk1, const float* __restrict__ lt1,
                      const float* __restrict__ Wk2, const float* __restrict__ bk2, const float* __restrict__ lt2,
                      const float* __restrict__ Wk3, const float* __restrict__ bk3, const float* __restrict__ lt3)
{
    int tid = threadIdx.x;
    const float* Wk[3] = {Wk1, Wk2, Wk3};
    const float* bk[3] = {bk1, bk2, bk3};
    const float* lt[3] = {lt1, lt2, lt3};
    if (tid < 96) {
        int m = tid >> 5, d = tid & 31;
        float sa = Wq[d * 64 + 0];
        float sb = 0.f;
        #pragma unroll 1
        for (int j = 1; j < 64; j++) {
            float w = Wq[d * 64 + j];
            sa -= w * bk[m][j - 1];
            sb -= w * Wk[m][j - 1];
        }
        g_wa[m * DQIN + d] = sa;
        g_wb[m * DQIN + d] = sb;
        if (d == 0) {
            g_ca[m] = -bk[m][63];
            g_cb[m] = -Wk[m][63];
            g_invtau[m] = __expf(-lt[m][0]);
        }
    }
}

// ---------------------------------------------------------------------------
// prep2: V = data[:, :32] @ Wv + bv ; gather x = data[:, 33]
// ---------------------------------------------------------------------------
__global__ void prep2(const float* __restrict__ d1, const float* __restrict__ d2, const float* __restrict__ d3,
                      const float* __restrict__ Wv1, const float* __restrict__ bv1,
                      const float* __restrict__ Wv2, const float* __restrict__ bv2,
                      const float* __restrict__ Wv3, const float* __restrict__ bv3)
{
    int idx = blockIdx.x * blockDim.x + threadIdx.x;
    if (idx >= 3 * NB * LL * DV) return;
    int j   = idx & (DV - 1);
    int row = idx >> 6;
    int m   = row / (NB * LL);
    int r   = row - m * (NB * LL);

    const float* data = (m == 0 ? d1 : (m == 1 ? d2 : d3)) + (size_t)r * DF;
    const float* Wv   = (m == 0 ? Wv1 : (m == 1 ? Wv2 : Wv3));
    const float* bv   = (m == 0 ? bv1 : (m == 1 ? bv2 : bv3));

    float s = bv[j];
    #pragma unroll
    for (int i = 0; i < DQIN; i++)
        s = fmaf(data[i], Wv[i * 64 + j], s);
    g_V[idx] = s;
    if (j == 0) g_x[row] = data[33];
}

// ---------------------------------------------------------------------------
// prep1: per (m,n,t) alpha/beta, mask cutoff, softmax shift M. After prep2.
// ---------------------------------------------------------------------------
__global__ void prep1(const float* __restrict__ ref_data, const float* __restrict__ ref_t,
                      const float* __restrict__ t1, const float* __restrict__ t2,
                      const float* __restrict__ t3)
{
    int idx = blockIdx.x * blockDim.x + threadIdx.x;
    if (idx >= ROWS) return;
    int m = idx / (NB * TT);
    int r = idx - m * (NB * TT);
    int n = r / TT;
    int t = r - n * TT;

    const float* rd = ref_data + (size_t)(n * TT + t) * DQIN;
    float a = g_ca[m], b = g_cb[m];
    #pragma unroll
    for (int d = 0; d < DQIN; d++) {
        float v = rd[d];
        a = fmaf(v, g_wa[m * DQIN + d], a);
        b = fmaf(v, g_wb[m * DQIN + d], b);
    }
    g_alpha[idx] = a;
    g_beta[idx]  = b;

    const float* tl = (m == 0 ? t1 : (m == 1 ? t2 : t3)) + (size_t)n * LL;
    float rt = ref_t[n * TT + t];
    int lo = 0, hi = LL;
    while (lo < hi) {
        int mid = (lo + hi) >> 1;
        if (tl[mid] <= rt) lo = mid + 1; else hi = mid;
    }
    g_cut[idx] = lo;

    float M = 0.f;
    if (lo == LL) {
        const float* xg = g_x + (size_t)(m * NB + n) * LL;
        float minz2 = 3.4e38f;
        #pragma unroll 4
        for (int l = 0; l < LL; l++) {
            float z = fmaf(b, xg[l], a);
            minz2 = fminf(minz2, z * z);
        }
        M = -minz2 * g_invtau[m];
    }
    g_M[idx] = M;
}

// ---------------------------------------------------------------------------
// attn: two-phase tiled split-K attention.
// Phase A: weights w[k][q] (masked exactly) -> smem, no redundancy.
// Phase B: thread = 4 queries x 8 dims; acc = 16 ull (32 regs); FFMA2.
// ---------------------------------------------------------------------------
__global__ __launch_bounds__(128, 6)
void attn()
{
    __shared__ float  Ws[KT][TQ];    // 16 KB  weights [k][q]
    __shared__ float4 Vs[KT * 16];   // 16 KB  V tile  [k][dim/4]
    __shared__ float  xs[KT];
    __shared__ int    sred[4];

    const int bx   = blockIdx.x;            // 0..63
    const int csp  = bx & (KSPLIT - 1);
    const int tile = bx >> 1;                // 0..31
    const int n    = blockIdx.y;
    const int m    = blockIdx.z;
    const int tid  = threadIdx.x;

    const int rowbase = (m * NB + n) * TT;
    const int t0      = tile * TQ;
    const int cstart  = csp * CHUNK;
    const int cend    = cstart + CHUNK;

    const float c1 = -g_invtau[m] * LOG2E;

    // ----- phase A thread mapping: 4 queries x 8 keys per tile -----
    const int qa = (tid & 15) * 4;
    const int ks = tid >> 4;                 // 0..7

    float aA[4], bA[4], cA[4];
    int   limA[4];
    int   tmax = 0;
    #pragma unroll
    for (int j = 0; j < 4; j++) {
        int rr = rowbase + t0 + qa + j;
        aA[j]   = g_alpha[rr];
        bA[j]   = g_beta[rr];
        cA[j]   = -g_M[rr] * LOG2E;
        limA[j] = g_cut[rr];
        tmax = max(tmax, min(limA[j], cend));
    }
    int wmax = __reduce_max_sync(0xffffffffu, tmax);
    if ((tid & 31) == 0) sred[tid >> 5] = wmax;
    __syncthreads();
    const int bend = max(max(sred[0], sred[1]), max(sred[2], sred[3]));

    // ----- phase B thread mapping: 4 queries x 8 dims -----
    const int qb = (tid >> 3) * 4;
    const int dg = tid & 7;

    ull acc[4][4];
    #pragma unroll
    for (int j = 0; j < 4; j++)
        #pragma unroll
        for (int i = 0; i < 4; i++) acc[j][i] = 0ull;
    float den[4] = {0.f, 0.f, 0.f, 0.f};

    const float*  xg  = g_x + (size_t)(m * NB + n) * LL;
    const float4* Vg4 = (const float4*)(g_V + (size_t)(m * NB + n) * LL * DV);

    for (int base = cstart; base < bend; base += KT) {
        __syncthreads();   // previous phase B done (also pairs with sred sync first iter)

        // load V tile (64 rows x 16 float4) + x tile
        #pragma unroll
        for (int i = 0; i < 8; i++)
            Vs[tid + i * 128] = Vg4[base * 16 + tid + i * 128];
        if (tid < KT) xs[tid] = xg[base + tid];

        // phase A: 8 keys x 4 queries per thread, masked weights -> Ws
        #pragma unroll
        for (int i = 0; i < 8; i++) {
            int kk = ks * 8 + i;
            float x = xg[base + kk];        // L1-cached broadcast
            float e[4];
            #pragma unroll
            for (int j = 0; j < 4; j++) {
                float z  = fmaf(bA[j], x, aA[j]);
                float ee = ex2(fmaf(z * z, c1, cA[j]));
                e[j] = ((base + kk) < limA[j]) ? ee : 0.f;
            }
            *(float4*)&Ws[kk][qa] = make_float4(e[0], e[1], e[2], e[3]);
        }
        __syncthreads();

        // phase B: accumulate full tile (masked entries are zero)
        #pragma unroll 4
        for (int k = 0; k < KT; k++) {
            float4 w4 = *(const float4*)&Ws[k][qb];
            const ulonglong2* vp = (const ulonglong2*)&Vs[k * 16 + dg * 2];
            ulonglong2 v0 = vp[0];
            ulonglong2 v1 = vp[1];
            float wv[4] = {w4.x, w4.y, w4.z, w4.w};
            #pragma unroll
            for (int j = 0; j < 4; j++) {
                den[j] += wv[j];
                ull e2 = pack2(wv[j]);
                fma2(acc[j][0], e2, v0.x);
                fma2(acc[j][1], e2, v0.y);
                fma2(acc[j][2], e2, v1.x);
                fma2(acc[j][3], e2, v1.y);
            }
        }
    }

    // write partials (all blocks, incl. empty -> zeros; deterministic)
    if (dg == 0) {
        float* pp = g_pden + (size_t)csp * ROWS + rowbase + t0 + qb;
        #pragma unroll
        for (int j = 0; j < 4; j++) pp[j] = den[j];
    }
    #pragma unroll
    for (int j = 0; j < 4; j++) {
        float4* op = (float4*)(g_part + (((size_t)csp * ROWS + rowbase + t0 + qb + j) << 6) + dg * 8);
        float2 p0 = *(float2*)&acc[j][0];
        float2 p1 = *(float2*)&acc[j][1];
        float2 p2 = *(float2*)&acc[j][2];
        float2 p3 = *(float2*)&acc[j][3];
        op[0] = make_float4(p0.x, p0.y, p1.x, p1.y);
        op[1] = make_float4(p2.x, p2.y, p3.x, p3.y);
    }
}

// ---------------------------------------------------------------------------
// combine: out = (sum_c part) / (sum_c pden + (LL - cut))
// ---------------------------------------------------------------------------
__global__ void combine(float* __restrict__ out)
{
    int idx = blockIdx.x * blockDim.x + threadIdx.x;   // ROWS * 16 float4s
    if (idx >= ROWS * 16) return;
    int row = idx >> 4;
    int f   = idx & 15;

    float4 s = make_float4(0.f, 0.f, 0.f, 0.f);
    float den = (float)(LL - g_cut[row]);
    #pragma unroll
    for (int c = 0; c < KSPLIT; c++) {
        const float4* p = (const float4*)(g_part + (((size_t)c * ROWS + row) << 6));
        float4 v = p[f];
        s.x += v.x; s.y += v.y; s.z += v.z; s.w += v.w;
        den += g_pden[c * ROWS + row];
    }
    float inv = 1.f / den;
    ((float4*)out)[idx] = make_float4(s.x * inv, s.y * inv, s.z * inv, s.w * inv);
}

// ---------------------------------------------------------------------------
extern "C" void kernel_launch(void* const* d_in, const int* in_sizes, int n_in,
                              void* d_out, int out_size)
{
    const float* ref_data = (const float*)d_in[0];
    const float* ref_t    = (const float*)d_in[1];
    const float* m1_data  = (const float*)d_in[2];
    const float* m1_t     = (const float*)d_in[3];
    const float* m2_data  = (const float*)d_in[4];
    const float* m2_t     = (const float*)d_in[5];
    const float* m3_data  = (const float*)d_in[6];
    const float* m3_t     = (const float*)d_in[7];
    const float* Wq       = (const float*)d_in[8];
    const float* Wk1      = (const float*)d_in[9];
    const float* bk1      = (const float*)d_in[10];
    const float* Wv1      = (const float*)d_in[11];
    const float* bv1      = (const float*)d_in[12];
    const float* lt1      = (const float*)d_in[13];
    const float* Wk2      = (const float*)d_in[14];
    const float* bk2      = (const float*)d_in[15];
    const float* Wv2      = (const float*)d_in[16];
    const float* bv2      = (const float*)d_in[17];
    const float* lt2      = (const float*)d_in[18];
    const float* Wk3      = (const float*)d_in[19];
    const float* bk3      = (const float*)d_in[20];
    const float* Wv3      = (const float*)d_in[21];
    const float* bv3      = (const float*)d_in[22];
    const float* lt3      = (const float*)d_in[23];

    prep0<<<1, 128>>>(Wq, Wk1, bk1, lt1, Wk2, bk2, lt2, Wk3, bk3, lt3);
    prep2<<<(3 * NB * LL * DV) / 256, 256>>>(m1_data, m2_data, m3_data,
                                             Wv1, bv1, Wv2, bv2, Wv3, bv3);
    prep1<<<(ROWS + 127) / 128, 128>>>(ref_data, ref_t, m1_t, m2_t, m3_t);
    attn<<<dim3((TT / TQ) * KSPLIT, NB, 3), 128>>>();
    combine<<<(ROWS * 16 + 255) / 256, 256>>>((float*)d_out);
}

// round 7
// speedup vs baseline: 4.4434x; 2.9914x over previous
#include <cuda_runtime.h>
#include <cuda_bf16.h>
#include <cstdint>

#define NB   4
#define TT   2048
#define LL   2048
#define DV   64
#define DQIN 32
#define DF   34
#define ROWS (3 * NB * TT)      // 24576
#define KSPLIT 2
#define CHUNK  (LL / KSPLIT)    // 1024
#define KT   64                 // keys staged per smem tile
#define TQ   64                 // queries per block (4 warps x 16)
#define VSS  72                 // padded Vs row stride (floats) -> conflict-free B frags
#define LOG2E 1.4426950408889634f

// Scratch (device globals; no allocation allowed)
__device__ float g_V[3 * NB * LL * DV];          // 6 MB  tf32 V rows [mn][l][d]
__device__ float g_x[3 * NB * LL];
__device__ float g_alpha[ROWS];
__device__ float g_beta[ROWS];
__device__ int   g_cut[ROWS];
__device__ float g_M[ROWS];
__device__ float g_wa[3 * DQIN];
__device__ float g_wb[3 * DQIN];
__device__ float g_ca[3];
__device__ float g_cb[3];
__device__ float g_invtau[3];
__device__ float g_part[(size_t)KSPLIT * ROWS * DV];  // 12.6 MB
__device__ float g_pden[KSPLIT * ROWS];

__device__ __forceinline__ float ex2(float x) {
    float r; asm("ex2.approx.f32 %0, %1;" : "=f"(r) : "f"(x)); return r;
}
__device__ __forceinline__ uint32_t to_tf32(float x) {
    uint32_t u; asm("cvt.rna.tf32.f32 %0, %1;" : "=r"(u) : "f"(x)); return u;
}
// m16n8k8 tf32 MMA: D += A(16x8) * B(8x8)
__device__ __forceinline__ void mma8(float* d, uint32_t a0, uint32_t a1, uint32_t a2, uint32_t a3,
                                     uint32_t b0, uint32_t b1) {
    asm volatile(
        "mma.sync.aligned.m16n8k8.row.col.f32.tf32.tf32.f32 "
        "{%0,%1,%2,%3}, {%4,%5,%6,%7}, {%8,%9}, {%0,%1,%2,%3};"
        : "+f"(d[0]), "+f"(d[1]), "+f"(d[2]), "+f"(d[3])
        : "r"(a0), "r"(a1), "r"(a2), "r"(a3), "r"(b0), "r"(b1));
}

// ---------------------------------------------------------------------------
// prep0: collapse K-path weights.  Q.K = alpha + beta * x
// ---------------------------------------------------------------------------
__global__ void prep0(const float* __restrict__ Wq,
                      const float* __restrict__ Wk1, const float* __restrict__ bk1, const float* __restrict__ lt1,
                      const float* __restrict__ Wk2, const float* __restrict__ bk2, const float* __restrict__ lt2,
                      const float* __restrict__ Wk3, const float* __restrict__ bk3, const float* __restrict__ lt3)
{
    int tid = threadIdx.x;
    const float* Wk[3] = {Wk1, Wk2, Wk3};
    const float* bk[3] = {bk1, bk2, bk3};
    const float* lt[3] = {lt1, lt2, lt3};
    if (tid < 96) {
        int m = tid >> 5, d = tid & 31;
        float sa = Wq[d * 64 + 0];
        float sb = 0.f;
        #pragma unroll 1
        for (int j = 1; j < 64; j++) {
            float w = Wq[d * 64 + j];
            sa -= w * bk[m][j - 1];
            sb -= w * Wk[m][j - 1];
        }
        g_wa[m * DQIN + d] = sa;
        g_wb[m * DQIN + d] = sb;
        if (d == 0) {
            g_ca[m] = -bk[m][63];
            g_cb[m] = -Wk[m][63];
            g_invtau[m] = __expf(-lt[m][0]);
        }
    }
}

// ---------------------------------------------------------------------------
// prep2: V[mn][l][d] = tf32( data[l][:32] @ Wv + bv ) ; g_x = data[:,33]
// ---------------------------------------------------------------------------
__global__ __launch_bounds__(256)
void prep2(const float* __restrict__ d1, const float* __restrict__ d2, const float* __restrict__ d3,
           const float* __restrict__ Wv1, const float* __restrict__ bv1,
           const float* __restrict__ Wv2, const float* __restrict__ bv2,
           const float* __restrict__ Wv3, const float* __restrict__ bv3)
{
    int idx = blockIdx.x * blockDim.x + threadIdx.x;
    if (idx >= 3 * NB * LL * DV) return;
    int j   = idx & (DV - 1);
    int row = idx >> 6;                 // m*NB*LL + n*LL + l
    int m   = row / (NB * LL);
    int r   = row - m * (NB * LL);

    const float* data = (m == 0 ? d1 : (m == 1 ? d2 : d3)) + (size_t)r * DF;
    const float* Wv   = (m == 0 ? Wv1 : (m == 1 ? Wv2 : Wv3));
    const float* bv   = (m == 0 ? bv1 : (m == 1 ? bv2 : bv3));

    float s = __ldg(bv + j);
    #pragma unroll
    for (int i = 0; i < DQIN; i++)
        s = fmaf(data[i], __ldg(Wv + i * 64 + j), s);
    g_V[idx] = __uint_as_float(to_tf32(s));
    if (j == 0) g_x[row] = data[33];
}

// ---------------------------------------------------------------------------
// prep1: alpha/beta, cutoff (smem binary search), softmax shift M.
// M-scan (cut==LL rows, rare) done COOPERATIVELY by the block. After prep2.
// ---------------------------------------------------------------------------
__global__ __launch_bounds__(256)
void prep1(const float* __restrict__ ref_data, const float* __restrict__ ref_t,
           const float* __restrict__ t1, const float* __restrict__ t2,
           const float* __restrict__ t3)
{
    __shared__ float tls[LL];        // 8 KB timeline
    __shared__ unsigned char s_flag[256];
    __shared__ float s_red[8];

    const int m = blockIdx.z;
    const int n = blockIdx.y;
    const int t = blockIdx.x * 256 + threadIdx.x;
    const int tid = threadIdx.x;
    const int idx = (m * NB + n) * TT + t;

    const float* tl = (m == 0 ? t1 : (m == 1 ? t2 : t3)) + (size_t)n * LL;
    for (int i = tid; i < LL; i += 256) tls[i] = tl[i];

    const float* rd = ref_data + (size_t)(n * TT + t) * DQIN;
    float a = g_ca[m], b = g_cb[m];
    #pragma unroll
    for (int d = 0; d < DQIN; d++) {
        float v = rd[d];
        a = fmaf(v, g_wa[m * DQIN + d], a);
        b = fmaf(v, g_wb[m * DQIN + d], b);
    }
    g_alpha[idx] = a;
    g_beta[idx]  = b;
    __syncthreads();

    float rt = ref_t[n * TT + t];
    int lo = 0, hi = LL;
    while (lo < hi) {
        int mid = (lo + hi) >> 1;
        if (tls[mid] <= rt) lo = mid + 1; else hi = mid;
    }
    g_cut[idx] = lo;
    g_M[idx]   = 0.f;
    s_flag[tid] = (lo == LL) ? 1 : 0;
    __syncthreads();

    // cooperative min-z^2 scan for flagged rows (few per block)
    const float* xg = g_x + (size_t)(m * NB + n) * LL;
    const float invtau = g_invtau[m];
    for (int tt = 0; tt < 256; tt++) {
        if (!s_flag[tt]) continue;
        int ridx = (m * NB + n) * TT + blockIdx.x * 256 + tt;
        float aa = g_alpha[ridx], bb = g_beta[ridx];
        float mn = 3.4e38f;
        #pragma unroll
        for (int j = 0; j < LL / 256; j++) {
            float z = fmaf(bb, xg[tid + j * 256], aa);
            mn = fminf(mn, z * z);
        }
        #pragma unroll
        for (int o = 16; o > 0; o >>= 1)
            mn = fminf(mn, __shfl_xor_sync(0xffffffffu, mn, o));
        if ((tid & 31) == 0) s_red[tid >> 5] = mn;
        __syncthreads();
        if (tid == 0) {
            float mm = s_red[0];
            #pragma unroll
            for (int i = 1; i < 8; i++) mm = fminf(mm, s_red[i]);
            g_M[ridx] = -mm * invtau;
        }
        __syncthreads();
    }
}

// ---------------------------------------------------------------------------
// attn: warp-level tf32 mma.sync flash attention, split-K.
// Block: 64 queries (4 warps x 16), 128 threads, key chunk of 1024.
// Per 8-key step: each thread computes its 4 A-fragment weights in registers
// (masked, tf32), B fragments read conflict-free from padded smem V tile,
// 8 HMMA accumulate D(16x64) in registers. Denominator via shfl reduce.
// ---------------------------------------------------------------------------
__global__ __launch_bounds__(128)
void attn()
{
    __shared__ float Vs[KT * VSS];   // 18 KB padded V tile [k][d]
    __shared__ float xs[KT];
    __shared__ int   s_red[4];

    const int bx   = blockIdx.x;
    const int csp  = bx & (KSPLIT - 1);
    const int tile = bx >> 1;            // 0..31
    const int n    = blockIdx.y;
    const int m    = blockIdx.z;
    const int tid  = threadIdx.x;
    const int w    = tid >> 5;
    const int lane = tid & 31;
    const int gid  = lane >> 2;          // groupID: q row
    const int tig  = lane & 3;           // thread-in-group: k col

    const int rowbase = (m * NB + n) * TT;
    const int t0      = tile * TQ;
    const int cstart  = csp * CHUNK;
    const int cend    = cstart + CHUNK;

    const float c1 = -g_invtau[m] * LOG2E;

    const int r0 = rowbase + t0 + w * 16 + gid;
    const int r1 = r0 + 8;
    const float aq0 = g_alpha[r0], bq0 = g_beta[r0], c20 = -g_M[r0] * LOG2E;
    const float aq1 = g_alpha[r1], bq1 = g_beta[r1], c21 = -g_M[r1] * LOG2E;
    const int lim0 = min(g_cut[r0], cend);
    const int lim1 = min(g_cut[r1], cend);

    const int wbend = __reduce_max_sync(0xffffffffu, max(lim0, lim1));
    if (lane == 0) s_red[w] = wbend;
    __syncthreads();
    const int bbend = max(max(s_red[0], s_red[1]), max(s_red[2], s_red[3]));

    const float* __restrict__ xg = g_x + (size_t)(m * NB + n) * LL;
    const float4* __restrict__ Vg4 = (const float4*)(g_V + ((size_t)(m * NB + n) * LL << 6));

    float acc[8][4];
    #pragma unroll
    for (int nt = 0; nt < 8; nt++)
        #pragma unroll
        for (int i = 0; i < 4; i++) acc[nt][i] = 0.f;
    float den0 = 0.f, den1 = 0.f;

    for (int base = cstart; base < bbend; base += KT) {
        __syncthreads();
        // stage V tile [64 k][64 d] into padded smem + x tile
        #pragma unroll
        for (int i = 0; i < 8; i++) {
            int e = tid + i * 128;
            int k = e >> 4, j = e & 15;
            *(float4*)&Vs[k * VSS + j * 4] = Vg4[((size_t)(base + k) << 4) + j];
        }
        if (tid < KT) xs[tid] = xg[base + tid];
        __syncthreads();

        if (base >= wbend) continue;

        #pragma unroll
        for (int kb = 0; kb < KT; kb += 8) {
            if (base + kb >= wbend) break;
            const int k0 = kb + tig, k1 = k0 + 4;
            const int kg0 = base + k0, kg1 = base + k1;
            const float x0 = xs[k0], x1 = xs[k1];

            float z, e0f, e1f, e2f, e3f;
            z = fmaf(bq0, x0, aq0); e0f = ex2(fmaf(z * z, c1, c20));
            z = fmaf(bq1, x0, aq1); e1f = ex2(fmaf(z * z, c1, c21));
            z = fmaf(bq0, x1, aq0); e2f = ex2(fmaf(z * z, c1, c20));
            z = fmaf(bq1, x1, aq1); e3f = ex2(fmaf(z * z, c1, c21));
            e0f = (kg0 < lim0) ? e0f : 0.f;
            e1f = (kg0 < lim1) ? e1f : 0.f;
            e2f = (kg1 < lim0) ? e2f : 0.f;
            e3f = (kg1 < lim1) ? e3f : 0.f;
            const uint32_t a0 = to_tf32(e0f), a1 = to_tf32(e1f);
            const uint32_t a2 = to_tf32(e2f), a3 = to_tf32(e3f);
            den0 += __uint_as_float(a0) + __uint_as_float(a2);
            den1 += __uint_as_float(a1) + __uint_as_float(a3);

            const uint32_t* vr0 = (const uint32_t*)&Vs[k0 * VSS + gid];
            const uint32_t* vr1 = (const uint32_t*)&Vs[k1 * VSS + gid];
            #pragma unroll
            for (int nt = 0; nt < 8; nt++)
                mma8(acc[nt], a0, a1, a2, a3, vr0[nt * 8], vr1[nt * 8]);
        }
    }

    // denominator: reduce over the 4 k-lanes of each q row
    den0 += __shfl_xor_sync(0xffffffffu, den0, 1);
    den0 += __shfl_xor_sync(0xffffffffu, den0, 2);
    den1 += __shfl_xor_sync(0xffffffffu, den1, 1);
    den1 += __shfl_xor_sync(0xffffffffu, den1, 2);
    if (tig == 0) {
        g_pden[csp * ROWS + r0] = den0;
        g_pden[csp * ROWS + r1] = den1;
    }

    // numerator partials: thread owns cols {2*tig, 2*tig+1} of each n-tile
    float* p0 = g_part + (((size_t)csp * ROWS + r0) << 6);
    float* p1 = g_part + (((size_t)csp * ROWS + r1) << 6);
    #pragma unroll
    for (int nt = 0; nt < 8; nt++) {
        *(float2*)(p0 + nt * 8 + 2 * tig) = make_float2(acc[nt][0], acc[nt][1]);
        *(float2*)(p1 + nt * 8 + 2 * tig) = make_float2(acc[nt][2], acc[nt][3]);
    }
}

// ---------------------------------------------------------------------------
// combine: out = (sum_c part) / (sum_c pden + (LL - cut))
// ---------------------------------------------------------------------------
__global__ void combine(float* __restrict__ out)
{
    int idx = blockIdx.x * blockDim.x + threadIdx.x;   // ROWS * 16 float4s
    if (idx >= ROWS * 16) return;
    int row = idx >> 4;
    int f   = idx & 15;

    float4 s = make_float4(0.f, 0.f, 0.f, 0.f);
    float den = (float)(LL - g_cut[row]);
    #pragma unroll
    for (int c = 0; c < KSPLIT; c++) {
        const float4* p = (const float4*)(g_part + (((size_t)c * ROWS + row) << 6));
        float4 v = p[f];
        s.x += v.x; s.y += v.y; s.z += v.z; s.w += v.w;
        den += g_pden[c * ROWS + row];
    }
    float inv = 1.f / den;
    ((float4*)out)[idx] = make_float4(s.x * inv, s.y * inv, s.z * inv, s.w * inv);
}

// ---------------------------------------------------------------------------
extern "C" void kernel_launch(void* const* d_in, const int* in_sizes, int n_in,
                              void* d_out, int out_size)
{
    const float* ref_data = (const float*)d_in[0];
    const float* ref_t    = (const float*)d_in[1];
    const float* m1_data  = (const float*)d_in[2];
    const float* m1_t     = (const float*)d_in[3];
    const float* m2_data  = (const float*)d_in[4];
    const float* m2_t     = (const float*)d_in[5];
    const float* m3_data  = (const float*)d_in[6];
    const float* m3_t     = (const float*)d_in[7];
    const float* Wq       = (const float*)d_in[8];
    const float* Wk1      = (const float*)d_in[9];
    const float* bk1      = (const float*)d_in[10];
    const float* Wv1      = (const float*)d_in[11];
    const float* bv1      = (const float*)d_in[12];
    const float* lt1      = (const float*)d_in[13];
    const float* Wk2      = (const float*)d_in[14];
    const float* bk2      = (const float*)d_in[15];
    const float* Wv2      = (const float*)d_in[16];
    const float* bv2      = (const float*)d_in[17];
    const float* lt2      = (const float*)d_in[18];
    const float* Wk3      = (const float*)d_in[19];
    const float* bk3      = (const float*)d_in[20];
    const float* Wv3      = (const float*)d_in[21];
    const float* bv3      = (const float*)d_in[22];
    const float* lt3      = (const float*)d_in[23];

    prep0<<<1, 128>>>(Wq, Wk1, bk1, lt1, Wk2, bk2, lt2, Wk3, bk3, lt3);
    prep2<<<(3 * NB * LL * DV) / 256, 256>>>(m1_data, m2_data, m3_data,
                                             Wv1, bv1, Wv2, bv2, Wv3, bv3);
    prep1<<<dim3(TT / 256, NB, 3), 256>>>(ref_data, ref_t, m1_t, m2_t, m3_t);
    attn<<<dim3((TT / TQ) * KSPLIT, NB, 3), 128>>>();
    combine<<<(ROWS * 16 + 255) / 256, 256>>>((float*)d_out);
}

// round 8
// speedup vs baseline: 5.1967x; 1.1695x over previous
#include <cuda_runtime.h>
#include <cuda_bf16.h>
#include <cstdint>

#define NB   4
#define TT   2048
#define LL   2048
#define DV   64
#define DQIN 32
#define DF   34
#define ROWS (3 * NB * TT)      // 24576
#define KSPLIT 4
#define CHUNK  (LL / KSPLIT)    // 512
#define KT   64                 // keys staged per smem tile
#define TQ   64                 // queries per block (4 warps x 16)
#define VSS  72                 // padded Vs row stride (floats) -> conflict-free B frags
#define LOG2E 1.4426950408889634f

// Scratch (device globals; no allocation allowed)
__device__ float g_V[3 * NB * LL * DV];          // 6 MB  tf32 V rows [mn][l][d]
__device__ float g_x[3 * NB * LL];
__device__ float g_alpha[ROWS];
__device__ float g_beta[ROWS];
__device__ int   g_cut[ROWS];
__device__ float g_M[ROWS];
__device__ float g_part[(size_t)KSPLIT * ROWS * DV];  // 25.2 MB
__device__ float g_pden[KSPLIT * ROWS];

__device__ __forceinline__ float ex2(float x) {
    float r; asm("ex2.approx.f32 %0, %1;" : "=f"(r) : "f"(x)); return r;
}
__device__ __forceinline__ uint32_t to_tf32(float x) {
    uint32_t u; asm("cvt.rna.tf32.f32 %0, %1;" : "=r"(u) : "f"(x)); return u;
}
// m16n8k8 tf32 MMA: D += A(16x8) * B(8x8)
__device__ __forceinline__ void mma8(float* d, uint32_t a0, uint32_t a1, uint32_t a2, uint32_t a3,
                                     uint32_t b0, uint32_t b1) {
    asm volatile(
        "mma.sync.aligned.m16n8k8.row.col.f32.tf32.tf32.f32 "
        "{%0,%1,%2,%3}, {%4,%5,%6,%7}, {%8,%9}, {%0,%1,%2,%3};"
        : "+f"(d[0]), "+f"(d[1]), "+f"(d[2]), "+f"(d[3])
        : "r"(a0), "r"(a1), "r"(a2), "r"(a3), "r"(b0), "r"(b1));
}

// ---------------------------------------------------------------------------
// prep (fused): grid (264, NB, 3), 256 threads.
//  blockIdx.x < 256 : V-GEMM role — V[mn][l][d] = tf32(data[l][:32]@Wv + bv),
//                     g_x[mn][l] = data[l][33]   (512 elems per block)
//  blockIdx.x >= 256: query role — collapse K-path weights in smem (redundant,
//                     tiny), then alpha/beta, mask cutoff (smem binary search),
//                     softmax shift M (cooperative, reads raw data col 33).
// Roles are independent -> latency-bound query blocks hide under GEMM blocks.
// ---------------------------------------------------------------------------
__global__ __launch_bounds__(256)
void prep(const float* __restrict__ ref_data, const float* __restrict__ ref_t,
          const float* __restrict__ d1, const float* __restrict__ t1,
          const float* __restrict__ d2, const float* __restrict__ t2,
          const float* __restrict__ d3, const float* __restrict__ t3,
          const float* __restrict__ Wq,
          const float* __restrict__ Wk1, const float* __restrict__ bk1,
          const float* __restrict__ Wv1, const float* __restrict__ bv1, const float* __restrict__ lt1,
          const float* __restrict__ Wk2, const float* __restrict__ bk2,
          const float* __restrict__ Wv2, const float* __restrict__ bv2, const float* __restrict__ lt2,
          const float* __restrict__ Wk3, const float* __restrict__ bk3,
          const float* __restrict__ Wv3, const float* __restrict__ bv3, const float* __restrict__ lt3)
{
    const int m   = blockIdx.z;
    const int n   = blockIdx.y;
    const int tid = threadIdx.x;
    const int mn  = m * NB + n;

    const float* dsrc = (m == 0 ? d1 : (m == 1 ? d2 : d3));

    if (blockIdx.x < 256) {
        // ---------------- V-GEMM role ----------------
        const float* Wv = (m == 0 ? Wv1 : (m == 1 ? Wv2 : Wv3));
        const float* bv = (m == 0 ? bv1 : (m == 1 ? bv2 : bv3));
        #pragma unroll
        for (int i = 0; i < 2; i++) {
            int e = blockIdx.x * 512 + tid + i * 256;   // 0..131071 within (m,n)
            int l = e >> 6, j = e & 63;
            const float* row = dsrc + (size_t)(n * LL + l) * DF;
            float s = __ldg(bv + j);
            #pragma unroll
            for (int q = 0; q < DQIN; q++)
                s = fmaf(row[q], __ldg(Wv + q * 64 + j), s);
            g_V[((size_t)mn << 17) + e] = __uint_as_float(to_tf32(s));
            if (j == 0) g_x[((size_t)mn << 11) + l] = row[33];
        }
        return;
    }

    // ---------------- query role ----------------
    __shared__ float tls[LL];                 // 8 KB timeline
    __shared__ float swa[DQIN], swb[DQIN];
    __shared__ float sconst[3];               // ca, cb, invtau
    __shared__ unsigned char s_flag[256];
    __shared__ float s_red[8];

    const float* Wk = (m == 0 ? Wk1 : (m == 1 ? Wk2 : Wk3));
    const float* bk = (m == 0 ? bk1 : (m == 1 ? bk2 : bk3));
    const float* lt = (m == 0 ? lt1 : (m == 1 ? lt2 : lt3));
    const float* tl = (m == 0 ? t1 : (m == 1 ? t2 : t3)) + (size_t)n * LL;

    const int t   = (blockIdx.x - 256) * 256 + tid;
    const int idx = mn * TT + t;

    for (int i = tid; i < LL; i += 256) tls[i] = tl[i];
    if (tid < DQIN) {
        int d = tid;
        float sa = Wq[d * 64 + 0];
        float sb = 0.f;
        #pragma unroll 1
        for (int j = 1; j < 64; j++) {
            float w = Wq[d * 64 + j];
            sa -= w * bk[j - 1];
            sb -= w * Wk[j - 1];
        }
        swa[d] = sa;
        swb[d] = sb;
        if (d == 0) {
            sconst[0] = -bk[63];
            sconst[1] = -Wk[63];
            sconst[2] = __expf(-lt[0]);
        }
    }
    __syncthreads();

    const float* rd = ref_data + (size_t)(n * TT + t) * DQIN;
    float a = sconst[0], b = sconst[1];
    #pragma unroll
    for (int d = 0; d < DQIN; d++) {
        float v = rd[d];
        a = fmaf(v, swa[d], a);
        b = fmaf(v, swb[d], b);
    }
    g_alpha[idx] = a;
    g_beta[idx]  = b;

    float rt = ref_t[n * TT + t];
    int lo = 0, hi = LL;
    while (lo < hi) {
        int mid = (lo + hi) >> 1;
        if (tls[mid] <= rt) lo = mid + 1; else hi = mid;
    }
    g_cut[idx] = lo;
    g_M[idx]   = 0.f;
    s_flag[tid] = (lo == LL) ? 1 : 0;
    __syncthreads();

    // cooperative min-z^2 scan for flagged rows (rare) — x read from raw data
    const float invtau = sconst[2];
    for (int tt = 0; tt < 256; tt++) {
        if (!s_flag[tt]) continue;                 // uniform (smem) branch
        int ridx = mn * TT + (blockIdx.x - 256) * 256 + tt;
        float aa = g_alpha[ridx], bb = g_beta[ridx];
        float mnv = 3.4e38f;
        #pragma unroll
        for (int j = 0; j < LL / 256; j++) {
            float x = dsrc[(size_t)(n * LL + tid + j * 256) * DF + 33];
            float z = fmaf(bb, x, aa);
            mnv = fminf(mnv, z * z);
        }
        #pragma unroll
        for (int o = 16; o > 0; o >>= 1)
            mnv = fminf(mnv, __shfl_xor_sync(0xffffffffu, mnv, o));
        if ((tid & 31) == 0) s_red[tid >> 5] = mnv;
        __syncthreads();
        if (tid == 0) {
            float mm = s_red[0];
            #pragma unroll
            for (int i = 1; i < 8; i++) mm = fminf(mm, s_red[i]);
            g_M[ridx] = -mm * invtau;
        }
        __syncthreads();
    }
}

// ---------------------------------------------------------------------------
// attn: warp-level tf32 mma.sync flash attention, split-K (KSPLIT=4).
// Block: 64 queries (4 warps x 16), 128 threads, key chunk of 512.
// ---------------------------------------------------------------------------
__global__ __launch_bounds__(128)
void attn(const float* __restrict__ lt1, const float* __restrict__ lt2,
          const float* __restrict__ lt3)
{
    __shared__ float Vs[KT * VSS];   // 18 KB padded V tile [k][d]
    __shared__ float xs[KT];
    __shared__ int   s_red[4];

    const int bx   = blockIdx.x;
    const int csp  = bx & (KSPLIT - 1);
    const int tile = bx >> 2;            // 0..31
    const int n    = blockIdx.y;
    const int m    = blockIdx.z;
    const int tid  = threadIdx.x;
    const int w    = tid >> 5;
    const int lane = tid & 31;
    const int gid  = lane >> 2;          // groupID: q row
    const int tig  = lane & 3;           // thread-in-group: k col

    const int rowbase = (m * NB + n) * TT;
    const int t0      = tile * TQ;
    const int cstart  = csp * CHUNK;
    const int cend    = cstart + CHUNK;

    const float* lt = (m == 0 ? lt1 : (m == 1 ? lt2 : lt3));
    const float c1 = -__expf(-lt[0]) * LOG2E;

    const int r0 = rowbase + t0 + w * 16 + gid;
    const int r1 = r0 + 8;
    const float aq0 = g_alpha[r0], bq0 = g_beta[r0], c20 = -g_M[r0] * LOG2E;
    const float aq1 = g_alpha[r1], bq1 = g_beta[r1], c21 = -g_M[r1] * LOG2E;
    const int lim0 = min(g_cut[r0], cend);
    const int lim1 = min(g_cut[r1], cend);

    const int wbend = __reduce_max_sync(0xffffffffu, max(lim0, lim1));
    if (lane == 0) s_red[w] = wbend;
    __syncthreads();
    const int bbend = max(max(s_red[0], s_red[1]), max(s_red[2], s_red[3]));

    const float* __restrict__ xg = g_x + (size_t)(m * NB + n) * LL;
    const float4* __restrict__ Vg4 = (const float4*)(g_V + ((size_t)(m * NB + n) * LL << 6));

    float acc[8][4];
    #pragma unroll
    for (int nt = 0; nt < 8; nt++)
        #pragma unroll
        for (int i = 0; i < 4; i++) acc[nt][i] = 0.f;
    float den0 = 0.f, den1 = 0.f;

    for (int base = cstart; base < bbend; base += KT) {
        __syncthreads();
        // stage V tile [64 k][64 d] into padded smem + x tile
        #pragma unroll
        for (int i = 0; i < 8; i++) {
            int e = tid + i * 128;
            int k = e >> 4, j = e & 15;
            *(float4*)&Vs[k * VSS + j * 4] = Vg4[((size_t)(base + k) << 4) + j];
        }
        if (tid < KT) xs[tid] = xg[base + tid];
        __syncthreads();

        if (base >= wbend) continue;

        #pragma unroll
        for (int kb = 0; kb < KT; kb += 8) {
            if (base + kb >= wbend) break;
            const int k0 = kb + tig, k1 = k0 + 4;
            const int kg0 = base + k0, kg1 = base + k1;
            const float x0 = xs[k0], x1 = xs[k1];

            float z, e0f, e1f, e2f, e3f;
            z = fmaf(bq0, x0, aq0); e0f = ex2(fmaf(z * z, c1, c20));
            z = fmaf(bq1, x0, aq1); e1f = ex2(fmaf(z * z, c1, c21));
            z = fmaf(bq0, x1, aq0); e2f = ex2(fmaf(z * z, c1, c20));
            z = fmaf(bq1, x1, aq1); e3f = ex2(fmaf(z * z, c1, c21));
            e0f = (kg0 < lim0) ? e0f : 0.f;
            e1f = (kg0 < lim1) ? e1f : 0.f;
            e2f = (kg1 < lim0) ? e2f : 0.f;
            e3f = (kg1 < lim1) ? e3f : 0.f;
            const uint32_t a0 = to_tf32(e0f), a1 = to_tf32(e1f);
            const uint32_t a2 = to_tf32(e2f), a3 = to_tf32(e3f);
            den0 += __uint_as_float(a0) + __uint_as_float(a2);
            den1 += __uint_as_float(a1) + __uint_as_float(a3);

            const uint32_t* vr0 = (const uint32_t*)&Vs[k0 * VSS + gid];
            const uint32_t* vr1 = (const uint32_t*)&Vs[k1 * VSS + gid];
            #pragma unroll
            for (int nt = 0; nt < 8; nt++)
                mma8(acc[nt], a0, a1, a2, a3, vr0[nt * 8], vr1[nt * 8]);
        }
    }

    // denominator: reduce over the 4 k-lanes of each q row
    den0 += __shfl_xor_sync(0xffffffffu, den0, 1);
    den0 += __shfl_xor_sync(0xffffffffu, den0, 2);
    den1 += __shfl_xor_sync(0xffffffffu, den1, 1);
    den1 += __shfl_xor_sync(0xffffffffu, den1, 2);
    if (tig == 0) {
        g_pden[csp * ROWS + r0] = den0;
        g_pden[csp * ROWS + r1] = den1;
    }

    // numerator partials: thread owns cols {2*tig, 2*tig+1} of each n-tile
    float* p0 = g_part + (((size_t)csp * ROWS + r0) << 6);
    float* p1 = g_part + (((size_t)csp * ROWS + r1) << 6);
    #pragma unroll
    for (int nt = 0; nt < 8; nt++) {
        *(float2*)(p0 + nt * 8 + 2 * tig) = make_float2(acc[nt][0], acc[nt][1]);
        *(float2*)(p1 + nt * 8 + 2 * tig) = make_float2(acc[nt][2], acc[nt][3]);
    }
}

// ---------------------------------------------------------------------------
// combine: out = (sum_c part) / (sum_c pden + (LL - cut))
// ---------------------------------------------------------------------------
__global__ void combine(float* __restrict__ out)
{
    int idx = blockIdx.x * blockDim.x + threadIdx.x;   // ROWS * 16 float4s
    if (idx >= ROWS * 16) return;
    int row = idx >> 4;
    int f   = idx & 15;

    float4 s = make_float4(0.f, 0.f, 0.f, 0.f);
    float den = (float)(LL - g_cut[row]);
    #pragma unroll
    for (int c = 0; c < KSPLIT; c++) {
        const float4* p = (const float4*)(g_part + (((size_t)c * ROWS + row) << 6));
        float4 v = p[f];
        s.x += v.x; s.y += v.y; s.z += v.z; s.w += v.w;
        den += g_pden[c * ROWS + row];
    }
    float inv = 1.f / den;
    ((float4*)out)[idx] = make_float4(s.x * inv, s.y * inv, s.z * inv, s.w * inv);
}

// ---------------------------------------------------------------------------
extern "C" void kernel_launch(void* const* d_in, const int* in_sizes, int n_in,
                              void* d_out, int out_size)
{
    const float* ref_data = (const float*)d_in[0];
    const float* ref_t    = (const float*)d_in[1];
    const float* m1_data  = (const float*)d_in[2];
    const float* m1_t     = (const float*)d_in[3];
    const float* m2_data  = (const float*)d_in[4];
    const float* m2_t     = (const float*)d_in[5];
    const float* m3_data  = (const float*)d_in[6];
    const float* m3_t     = (const float*)d_in[7];
    const float* Wq       = (const float*)d_in[8];
    const float* Wk1      = (const float*)d_in[9];
    const float* bk1      = (const float*)d_in[10];
    const float* Wv1      = (const float*)d_in[11];
    const float* bv1      = (const float*)d_in[12];
    const float* lt1      = (const float*)d_in[13];
    const float* Wk2      = (const float*)d_in[14];
    const float* bk2      = (const float*)d_in[15];
    const float* Wv2      = (const float*)d_in[16];
    const float* bv2      = (const float*)d_in[17];
    const float* lt2      = (const float*)d_in[18];
    const float* Wk3      = (const float*)d_in[19];
    const float* bk3      = (const float*)d_in[20];
    const float* Wv3      = (const float*)d_in[21];
    const float* bv3      = (const float*)d_in[22];
    const float* lt3      = (const float*)d_in[23];

    prep<<<dim3(256 + TT / 256, NB, 3), 256>>>(
        ref_data, ref_t, m1_data, m1_t, m2_data, m2_t, m3_data, m3_t, Wq,
        Wk1, bk1, Wv1, bv1, lt1,
        Wk2, bk2, Wv2, bv2, lt2,
        Wk3, bk3, Wv3, bv3, lt3);
    attn<<<dim3((TT / TQ) * KSPLIT, NB, 3), 128>>>(lt1, lt2, lt3);
    combine<<<(ROWS * 16 + 255) / 256, 256>>>((float*)d_out);
}

// round 12
// speedup vs baseline: 6.0073x; 1.1560x over previous
#include <cuda_runtime.h>
#include <cuda_bf16.h>
#include <cstdint>

#define NB   4
#define TT   2048
#define LL   2048
#define DV   64
#define DQIN 32
#define DF   34
#define ROWS (3 * NB * TT)      // 24576
#define KSPLIT 4
#define CHUNK  (LL / KSPLIT)    // 512
#define KT   64                 // keys staged per smem tile
#define TQ   64                 // queries per block (4 warps x 16)
#define VSS  72                 // padded Vs row stride (floats) -> conflict-free B frags
#define LOG2E 1.4426950408889634f

// Scratch (device globals; no allocation allowed)
__device__ float g_V[3 * NB * LL * DV];          // 6 MB  tf32 V rows [mn][l][d]
__device__ float g_x[3 * NB * LL];
__device__ float g_alpha[ROWS];
__device__ float g_beta[ROWS];
__device__ int   g_cut[ROWS];
__device__ float g_M[ROWS];
__device__ float g_part[(size_t)KSPLIT * ROWS * DV];  // 25.2 MB
__device__ float g_pden[KSPLIT * ROWS];

typedef unsigned long long ull;

__device__ __forceinline__ float ex2(float x) {
    float r; asm("ex2.approx.f32 %0, %1;" : "=f"(r) : "f"(x)); return r;
}
__device__ __forceinline__ uint32_t to_tf32(float x) {
    uint32_t u; asm("cvt.rna.tf32.f32 %0, %1;" : "=r"(u) : "f"(x)); return u;
}
__device__ __forceinline__ void fma2(ull& d, ull a, ull b) {
    asm("fma.rn.f32x2 %0, %1, %2, %0;" : "+l"(d) : "l"(a), "l"(b));
}
__device__ __forceinline__ ull pack2s(float x) {
    ull r; asm("mov.b64 %0, {%1, %1};" : "=l"(r) : "f"(x)); return r;
}
__device__ __forceinline__ ull pack2(float x, float y) {
    ull r; asm("mov.b64 %0, {%1, %2};" : "=l"(r) : "f"(x), "f"(y)); return r;
}
// m16n8k8 tf32 MMA: D += A(16x8) * B(8x8)
__device__ __forceinline__ void mma8(float* d, uint32_t a0, uint32_t a1, uint32_t a2, uint32_t a3,
                                     uint32_t b0, uint32_t b1) {
    asm volatile(
        "mma.sync.aligned.m16n8k8.row.col.f32.tf32.tf32.f32 "
        "{%0,%1,%2,%3}, {%4,%5,%6,%7}, {%8,%9}, {%0,%1,%2,%3};"
        : "+f"(d[0]), "+f"(d[1]), "+f"(d[2]), "+f"(d[3])
        : "r"(a0), "r"(a1), "r"(a2), "r"(a3), "r"(b0), "r"(b1));
}

#define DSS 38   // padded smem data row stride (floats)
#define WSS 72   // padded smem Wv row stride

// ---------------------------------------------------------------------------
// prep (fused): grid (24, NB, 3), 256 threads.
//  blockIdx.x < 16 : V-GEMM role — smem-staged block GEMM:
//     V[mn][l][d] = tf32(data[l][:32]@Wv + bv), g_x[mn][l] = data[l][33]
//     128 rows per block; thread = 4 rows x 8 dims, FFMA2 from smem.
//  blockIdx.x >= 16: query role — collapse K-path weights in smem, then
//     alpha/beta, mask cutoff (smem binary search), softmax shift M.
// NOTE: every shared array read through a vector cast is alignas(16).
// ---------------------------------------------------------------------------
__global__ __launch_bounds__(256)
void prep(const float* __restrict__ ref_data, const float* __restrict__ ref_t,
          const float* __restrict__ d1, const float* __restrict__ t1,
          const float* __restrict__ d2, const float* __restrict__ t2,
          const float* __restrict__ d3, const float* __restrict__ t3,
          const float* __restrict__ Wq,
          const float* __restrict__ Wk1, const float* __restrict__ bk1,
          const float* __restrict__ Wv1, const float* __restrict__ bv1, const float* __restrict__ lt1,
          const float* __restrict__ Wk2, const float* __restrict__ bk2,
          const float* __restrict__ Wv2, const float* __restrict__ bv2, const float* __restrict__ lt2,
          const float* __restrict__ Wk3, const float* __restrict__ bk3,
          const float* __restrict__ Wv3, const float* __restrict__ bv3, const float* __restrict__ lt3)
{
    const int m   = blockIdx.z;
    const int n   = blockIdx.y;
    const int tid = threadIdx.x;
    const int mn  = m * NB + n;

    const float* dsrc = (m == 0 ? d1 : (m == 1 ? d2 : d3));

    if (blockIdx.x < 16) {
        // ---------------- V-GEMM role ----------------
        __shared__ alignas(16) float sD[128 * DSS];   // 19 KB staged data rows
        __shared__ alignas(16) float sW[DQIN * WSS];  // 9 KB  padded Wv
        __shared__ alignas(16) float sbv[DV];

        const float* Wv = (m == 0 ? Wv1 : (m == 1 ? Wv2 : Wv3));
        const float* bv = (m == 0 ? bv1 : (m == 1 ? bv2 : bv3));
        const int l0 = blockIdx.x * 128;

        for (int i = tid; i < DQIN * DV; i += 256)
            sW[(i >> 6) * WSS + (i & 63)] = Wv[i];
        if (tid < DV) sbv[tid] = bv[tid];

        // stage 128 rows x 34 floats, coalesced float2 (row pitch 136 B, 8B-aligned)
        const float2* src = (const float2*)(dsrc + (size_t)(n * LL + l0) * DF);
        #pragma unroll
        for (int i = tid; i < 128 * (DF / 2); i += 256) {
            int r = i / (DF / 2), c = i - r * (DF / 2);
            *(float2*)&sD[r * DSS + c * 2] = src[i];
        }
        __syncthreads();

        // thread = rows {lr*4 .. lr*4+3} x dims {jg*8 .. jg*8+7}
        const int jg = tid & 7;
        const int lr = tid >> 3;

        ull acc[4][4];
        {
            ull b0 = pack2(sbv[jg * 8 + 0], sbv[jg * 8 + 1]);
            ull b1 = pack2(sbv[jg * 8 + 2], sbv[jg * 8 + 3]);
            ull b2 = pack2(sbv[jg * 8 + 4], sbv[jg * 8 + 5]);
            ull b3 = pack2(sbv[jg * 8 + 6], sbv[jg * 8 + 7]);
            #pragma unroll
            for (int rr = 0; rr < 4; rr++) {
                acc[rr][0] = b0; acc[rr][1] = b1; acc[rr][2] = b2; acc[rr][3] = b3;
            }
        }
        #pragma unroll 8
        for (int q = 0; q < DQIN; q++) {
            // WSS=72 floats = 288 B, jg*8 floats = 32 B -> 16B-aligned given alignas(16)
            const ulonglong2* wp = (const ulonglong2*)&sW[q * WSS + jg * 8];
            ulonglong2 w01 = wp[0];
            ulonglong2 w23 = wp[1];
            #pragma unroll
            for (int rr = 0; rr < 4; rr++) {
                ull x2 = pack2s(sD[(lr * 4 + rr) * DSS + q]);
                fma2(acc[rr][0], x2, w01.x);
                fma2(acc[rr][1], x2, w01.y);
                fma2(acc[rr][2], x2, w23.x);
                fma2(acc[rr][3], x2, w23.y);
            }
        }
        // convert to tf32, store
        #pragma unroll
        for (int rr = 0; rr < 4; rr++) {
            int l = lr * 4 + rr;
            float4 o0, o1;
            float2 p;
            p = *(float2*)&acc[rr][0]; o0.x = __uint_as_float(to_tf32(p.x)); o0.y = __uint_as_float(to_tf32(p.y));
            p = *(float2*)&acc[rr][1]; o0.z = __uint_as_float(to_tf32(p.x)); o0.w = __uint_as_float(to_tf32(p.y));
            p = *(float2*)&acc[rr][2]; o1.x = __uint_as_float(to_tf32(p.x)); o1.y = __uint_as_float(to_tf32(p.y));
            p = *(float2*)&acc[rr][3]; o1.z = __uint_as_float(to_tf32(p.x)); o1.w = __uint_as_float(to_tf32(p.y));
            float4* dst = (float4*)(g_V + ((size_t)mn << 17) + ((size_t)(l0 + l) << 6) + jg * 8);
            dst[0] = o0; dst[1] = o1;
        }
        if (tid < 128)
            g_x[((size_t)mn << 11) + l0 + tid] = sD[tid * DSS + 33];
        return;
    }

    // ---------------- query role ----------------
    __shared__ float tls[LL];                 // 8 KB timeline
    __shared__ float swa[DQIN], swb[DQIN];
    __shared__ float sconst[3];               // ca, cb, invtau
    __shared__ unsigned char s_flag[256];
    __shared__ float s_red[8];

    const float* Wk = (m == 0 ? Wk1 : (m == 1 ? Wk2 : Wk3));
    const float* bk = (m == 0 ? bk1 : (m == 1 ? bk2 : bk3));
    const float* lt = (m == 0 ? lt1 : (m == 1 ? lt2 : lt3));
    const float* tl = (m == 0 ? t1 : (m == 1 ? t2 : t3)) + (size_t)n * LL;

    const int t   = (blockIdx.x - 16) * 256 + tid;
    const int idx = mn * TT + t;

    for (int i = tid; i < LL; i += 256) tls[i] = tl[i];
    if (tid < DQIN) {
        int d = tid;
        float sa = Wq[d * 64 + 0];
        float sb = 0.f;
        #pragma unroll 1
        for (int j = 1; j < 64; j++) {
            float w = Wq[d * 64 + j];
            sa -= w * bk[j - 1];
            sb -= w * Wk[j - 1];
        }
        swa[d] = sa;
        swb[d] = sb;
        if (d == 0) {
            sconst[0] = -bk[63];
            sconst[1] = -Wk[63];
            sconst[2] = __expf(-lt[0]);
        }
    }
    __syncthreads();

    const float* rd = ref_data + (size_t)(n * TT + t) * DQIN;
    float a = sconst[0], b = sconst[1];
    #pragma unroll
    for (int d = 0; d < DQIN; d++) {
        float v = rd[d];
        a = fmaf(v, swa[d], a);
        b = fmaf(v, swb[d], b);
    }
    g_alpha[idx] = a;
    g_beta[idx]  = b;

    float rt = ref_t[n * TT + t];
    int lo = 0, hi = LL;
    while (lo < hi) {
        int mid = (lo + hi) >> 1;
        if (tls[mid] <= rt) lo = mid + 1; else hi = mid;
    }
    g_cut[idx] = lo;
    g_M[idx]   = 0.f;
    s_flag[tid] = (lo == LL) ? 1 : 0;
    __syncthreads();

    // cooperative min-z^2 scan for flagged rows (rare) — x read from raw data
    const float invtau = sconst[2];
    for (int tt = 0; tt < 256; tt++) {
        if (!s_flag[tt]) continue;                 // uniform (smem) branch
        int ridx = mn * TT + (blockIdx.x - 16) * 256 + tt;
        float aa = g_alpha[ridx], bb = g_beta[ridx];
        float mnv = 3.4e38f;
        #pragma unroll
        for (int j = 0; j < LL / 256; j++) {
            float x = dsrc[(size_t)(n * LL + tid + j * 256) * DF + 33];
            float z = fmaf(bb, x, aa);
            mnv = fminf(mnv, z * z);
        }
        #pragma unroll
        for (int o = 16; o > 0; o >>= 1)
            mnv = fminf(mnv, __shfl_xor_sync(0xffffffffu, mnv, o));
        if ((tid & 31) == 0) s_red[tid >> 5] = mnv;
        __syncthreads();
        if (tid == 0) {
            float mm = s_red[0];
            #pragma unroll
            for (int i = 1; i < 8; i++) mm = fminf(mm, s_red[i]);
            g_M[ridx] = -mm * invtau;
        }
        __syncthreads();
    }
}

// ---------------------------------------------------------------------------
// attn: warp-level tf32 mma.sync flash attention, split-K (KSPLIT=4).
// Block: 64 queries (4 warps x 16), 128 threads, key chunk of 512.
// ---------------------------------------------------------------------------
__global__ __launch_bounds__(128)
void attn(const float* __restrict__ lt1, const float* __restrict__ lt2,
          const float* __restrict__ lt3)
{
    __shared__ alignas(16) float Vs[KT * VSS];   // 18 KB padded V tile [k][d]
    __shared__ float xs[KT];
    __shared__ int   s_red[4];

    const int bx   = blockIdx.x;
    const int csp  = bx & (KSPLIT - 1);
    const int tile = bx >> 2;            // 0..31
    const int n    = blockIdx.y;
    const int m    = blockIdx.z;
    const int tid  = threadIdx.x;
    const int w    = tid >> 5;
    const int lane = tid & 31;
    const int gid  = lane >> 2;          // groupID: q row
    const int tig  = lane & 3;           // thread-in-group: k col

    const int rowbase = (m * NB + n) * TT;
    const int t0      = tile * TQ;
    const int cstart  = csp * CHUNK;
    const int cend    = cstart + CHUNK;

    const float* lt = (m == 0 ? lt1 : (m == 1 ? lt2 : lt3));
    const float c1 = -__expf(-lt[0]) * LOG2E;

    const int r0 = rowbase + t0 + w * 16 + gid;
    const int r1 = r0 + 8;
    const float aq0 = g_alpha[r0], bq0 = g_beta[r0], c20 = -g_M[r0] * LOG2E;
    const float aq1 = g_alpha[r1], bq1 = g_beta[r1], c21 = -g_M[r1] * LOG2E;
    const int lim0 = min(g_cut[r0], cend);
    const int lim1 = min(g_cut[r1], cend);

    const int wbend = __reduce_max_sync(0xffffffffu, max(lim0, lim1));
    if (lane == 0) s_red[w] = wbend;
    __syncthreads();
    const int bbend = max(max(s_red[0], s_red[1]), max(s_red[2], s_red[3]));

    const float* __restrict__ xg = g_x + (size_t)(m * NB + n) * LL;
    const float4* __restrict__ Vg4 = (const float4*)(g_V + ((size_t)(m * NB + n) * LL << 6));

    float acc[8][4];
    #pragma unroll
    for (int nt = 0; nt < 8; nt++)
        #pragma unroll
        for (int i = 0; i < 4; i++) acc[nt][i] = 0.f;
    float den0 = 0.f, den1 = 0.f;

    for (int base = cstart; base < bbend; base += KT) {
        __syncthreads();
        // stage V tile [64 k][64 d] into padded smem + x tile
        #pragma unroll
        for (int i = 0; i < 8; i++) {
            int e = tid + i * 128;
            int k = e >> 4, j = e & 15;
            *(float4*)&Vs[k * VSS + j * 4] = Vg4[((size_t)(base + k) << 4) + j];
        }
        if (tid < KT) xs[tid] = xg[base + tid];
        __syncthreads();

        if (base >= wbend) continue;

        #pragma unroll
        for (int kb = 0; kb < KT; kb += 8) {
            if (base + kb >= wbend) break;
            const int k0 = kb + tig, k1 = k0 + 4;
            const int kg0 = base + k0, kg1 = base + k1;
            const float x0 = xs[k0], x1 = xs[k1];

            float z, e0f, e1f, e2f, e3f;
            z = fmaf(bq0, x0, aq0); e0f = ex2(fmaf(z * z, c1, c20));
            z = fmaf(bq1, x0, aq1); e1f = ex2(fmaf(z * z, c1, c21));
            z = fmaf(bq0, x1, aq0); e2f = ex2(fmaf(z * z, c1, c20));
            z = fmaf(bq1, x1, aq1); e3f = ex2(fmaf(z * z, c1, c21));
            e0f = (kg0 < lim0) ? e0f : 0.f;
            e1f = (kg0 < lim1) ? e1f : 0.f;
            e2f = (kg1 < lim0) ? e2f : 0.f;
            e3f = (kg1 < lim1) ? e3f : 0.f;
            const uint32_t a0 = to_tf32(e0f), a1 = to_tf32(e1f);
            const uint32_t a2 = to_tf32(e2f), a3 = to_tf32(e3f);
            den0 += __uint_as_float(a0) + __uint_as_float(a2);
            den1 += __uint_as_float(a1) + __uint_as_float(a3);

            const uint32_t* vr0 = (const uint32_t*)&Vs[k0 * VSS + gid];
            const uint32_t* vr1 = (const uint32_t*)&Vs[k1 * VSS + gid];
            #pragma unroll
            for (int nt = 0; nt < 8; nt++)
                mma8(acc[nt], a0, a1, a2, a3, vr0[nt * 8], vr1[nt * 8]);
        }
    }

    // denominator: reduce over the 4 k-lanes of each q row
    den0 += __shfl_xor_sync(0xffffffffu, den0, 1);
    den0 += __shfl_xor_sync(0xffffffffu, den0, 2);
    den1 += __shfl_xor_sync(0xffffffffu, den1, 1);
    den1 += __shfl_xor_sync(0xffffffffu, den1, 2);
    if (tig == 0) {
        g_pden[csp * ROWS + r0] = den0;
        g_pden[csp * ROWS + r1] = den1;
    }

    // numerator partials: thread owns cols {2*tig, 2*tig+1} of each n-tile
    float* p0 = g_part + (((size_t)csp * ROWS + r0) << 6);
    float* p1 = g_part + (((size_t)csp * ROWS + r1) << 6);
    #pragma unroll
    for (int nt = 0; nt < 8; nt++) {
        *(float2*)(p0 + nt * 8 + 2 * tig) = make_float2(acc[nt][0], acc[nt][1]);
        *(float2*)(p1 + nt * 8 + 2 * tig) = make_float2(acc[nt][2], acc[nt][3]);
    }
}

// ---------------------------------------------------------------------------
// combine: out = (sum_c part) / (sum_c pden + (LL - cut))
// ---------------------------------------------------------------------------
__global__ void combine(float* __restrict__ out)
{
    int idx = blockIdx.x * blockDim.x + threadIdx.x;   // ROWS * 16 float4s
    if (idx >= ROWS * 16) return;
    int row = idx >> 4;
    int f   = idx & 15;

    float4 s = make_float4(0.f, 0.f, 0.f, 0.f);
    float den = (float)(LL - g_cut[row]);
    #pragma unroll
    for (int c = 0; c < KSPLIT; c++) {
        const float4* p = (const float4*)(g_part + (((size_t)c * ROWS + row) << 6));
        float4 v = p[f];
        s.x += v.x; s.y += v.y; s.z += v.z; s.w += v.w;
        den += g_pden[c * ROWS + row];
    }
    float inv = 1.f / den;
    ((float4*)out)[idx] = make_float4(s.x * inv, s.y * inv, s.z * inv, s.w * inv);
}

// ---------------------------------------------------------------------------
extern "C" void kernel_launch(void* const* d_in, const int* in_sizes, int n_in,
                              void* d_out, int out_size)
{
    const float* ref_data = (const float*)d_in[0];
    const float* ref_t    = (const float*)d_in[1];
    const float* m1_data  = (const float*)d_in[2];
    const float* m1_t     = (const float*)d_in[3];
    const float* m2_data  = (const float*)d_in[4];
    const float* m2_t     = (const float*)d_in[5];
    const float* m3_data  = (const float*)d_in[6];
    const float* m3_t     = (const float*)d_in[7];
    const float* Wq       = (const float*)d_in[8];
    const float* Wk1      = (const float*)d_in[9];
    const float* bk1      = (const float*)d_in[10];
    const float* Wv1      = (const float*)d_in[11];
    const float* bv1      = (const float*)d_in[12];
    const float* lt1      = (const float*)d_in[13];
    const float* Wk2      = (const float*)d_in[14];
    const float* bk2      = (const float*)d_in[15];
    const float* Wv2      = (const float*)d_in[16];
    const float* bv2      = (const float*)d_in[17];
    const float* lt2      = (const float*)d_in[18];
    const float* Wk3      = (const float*)d_in[19];
    const float* bk3      = (const float*)d_in[20];
    const float* Wv3      = (const float*)d_in[21];
    const float* bv3      = (const float*)d_in[22];
    const float* lt3      = (const float*)d_in[23];

    prep<<<dim3(16 + TT / 256, NB, 3), 256>>>(
        ref_data, ref_t, m1_data, m1_t, m2_data, m2_t, m3_data, m3_t, Wq,
        Wk1, bk1, Wv1, bv1, lt1,
        Wk2, bk2, Wv2, bv2, lt2,
        Wk3, bk3, Wv3, bv3, lt3);
    attn<<<dim3((TT / TQ) * KSPLIT, NB, 3), 128>>>(lt1, lt2, lt3);
    combine<<<(ROWS * 16 + 255) / 256, 256>>>((float*)d_out);
}

// round 13
// speedup vs baseline: 6.2295x; 1.0370x over previous
#include <cuda_runtime.h>
#include <cuda_bf16.h>
#include <cstdint>

#define NB   4
#define TT   2048
#define LL   2048
#define DV   64
#define DQIN 32
#define DF   34
#define ROWS (3 * NB * TT)      // 24576
#define KSPLIT 4
#define CHUNK  (LL / KSPLIT)    // 512
#define KT   64                 // keys staged per smem tile
#define TQ   64                 // queries per block (4 warps x 16)
#define VSS  72                 // padded Vs row stride (floats) -> conflict-free B frags
#define LOG2E 1.4426950408889634f

#define VBLOCKS 32              // V-GEMM blocks per (m,n): 64 rows each
#define QBLOCKS 16              // query blocks per (m,n): 128 queries each

// Scratch (device globals; no allocation allowed)
__device__ float g_V[3 * NB * LL * DV];          // 6 MB  tf32 V rows [mn][l][d]
__device__ float g_x[3 * NB * LL];
__device__ float g_alpha[ROWS];
__device__ float g_beta[ROWS];
__device__ int   g_cut[ROWS];
__device__ float g_M[ROWS];
__device__ float g_part[(size_t)KSPLIT * ROWS * DV];  // 25.2 MB
__device__ float g_pden[KSPLIT * ROWS];

typedef unsigned long long ull;

__device__ __forceinline__ float ex2(float x) {
    float r; asm("ex2.approx.f32 %0, %1;" : "=f"(r) : "f"(x)); return r;
}
__device__ __forceinline__ uint32_t to_tf32(float x) {
    uint32_t u; asm("cvt.rna.tf32.f32 %0, %1;" : "=r"(u) : "f"(x)); return u;
}
__device__ __forceinline__ void fma2(ull& d, ull a, ull b) {
    asm("fma.rn.f32x2 %0, %1, %2, %0;" : "+l"(d) : "l"(a), "l"(b));
}
__device__ __forceinline__ ull pack2s(float x) {
    ull r; asm("mov.b64 %0, {%1, %1};" : "=l"(r) : "f"(x)); return r;
}
__device__ __forceinline__ ull pack2(float x, float y) {
    ull r; asm("mov.b64 %0, {%1, %2};" : "=l"(r) : "f"(x), "f"(y)); return r;
}
// m16n8k8 tf32 MMA: D += A(16x8) * B(8x8)
__device__ __forceinline__ void mma8(float* d, uint32_t a0, uint32_t a1, uint32_t a2, uint32_t a3,
                                     uint32_t b0, uint32_t b1) {
    asm volatile(
        "mma.sync.aligned.m16n8k8.row.col.f32.tf32.tf32.f32 "
        "{%0,%1,%2,%3}, {%4,%5,%6,%7}, {%8,%9}, {%0,%1,%2,%3};"
        : "+f"(d[0]), "+f"(d[1]), "+f"(d[2]), "+f"(d[3])
        : "r"(a0), "r"(a1), "r"(a2), "r"(a3), "r"(b0), "r"(b1));
}

#define DSS 38   // padded smem data row stride (floats)
#define WSS 72   // padded smem Wv row stride

// ---------------------------------------------------------------------------
// prep (fused): grid (VBLOCKS+QBLOCKS, NB, 3), 256 threads.
//  blockIdx.x < VBLOCKS : V-GEMM role — smem-staged block GEMM, 64 rows:
//     V[mn][l][d] = tf32(data[l][:32]@Wv + bv), g_x[mn][l] = data[l][33]
//     thread = 2 rows x 8 dims, FFMA2 from smem.
//  else: query role — 128 queries: collapse K-path weights in smem, then
//     alpha/beta, mask cutoff (smem binary search), softmax shift M.
// ---------------------------------------------------------------------------
__global__ __launch_bounds__(256)
void prep(const float* __restrict__ ref_data, const float* __restrict__ ref_t,
          const float* __restrict__ d1, const float* __restrict__ t1,
          const float* __restrict__ d2, const float* __restrict__ t2,
          const float* __restrict__ d3, const float* __restrict__ t3,
          const float* __restrict__ Wq,
          const float* __restrict__ Wk1, const float* __restrict__ bk1,
          const float* __restrict__ Wv1, const float* __restrict__ bv1, const float* __restrict__ lt1,
          const float* __restrict__ Wk2, const float* __restrict__ bk2,
          const float* __restrict__ Wv2, const float* __restrict__ bv2, const float* __restrict__ lt2,
          const float* __restrict__ Wk3, const float* __restrict__ bk3,
          const float* __restrict__ Wv3, const float* __restrict__ bv3, const float* __restrict__ lt3)
{
    const int m   = blockIdx.z;
    const int n   = blockIdx.y;
    const int tid = threadIdx.x;
    const int mn  = m * NB + n;

    const float* dsrc = (m == 0 ? d1 : (m == 1 ? d2 : d3));

    if (blockIdx.x < VBLOCKS) {
        // ---------------- V-GEMM role: 64 rows ----------------
        __shared__ alignas(16) float sD[64 * DSS];    // 9.5 KB staged data rows
        __shared__ alignas(16) float sW[DQIN * WSS];  // 9 KB  padded Wv
        __shared__ alignas(16) float sbv[DV];

        const float* Wv = (m == 0 ? Wv1 : (m == 1 ? Wv2 : Wv3));
        const float* bv = (m == 0 ? bv1 : (m == 1 ? bv2 : bv3));
        const int l0 = blockIdx.x * 64;

        for (int i = tid; i < DQIN * DV; i += 256)
            sW[(i >> 6) * WSS + (i & 63)] = Wv[i];
        if (tid < DV) sbv[tid] = bv[tid];

        // stage 64 rows x 34 floats, coalesced float2 (row pitch 136 B, 8B-aligned)
        const float2* src = (const float2*)(dsrc + (size_t)(n * LL + l0) * DF);
        #pragma unroll
        for (int i = tid; i < 64 * (DF / 2); i += 256) {
            int r = i / (DF / 2), c = i - r * (DF / 2);
            *(float2*)&sD[r * DSS + c * 2] = src[i];
        }
        __syncthreads();

        // thread = rows {lr*2, lr*2+1} x dims {jg*8 .. jg*8+7}
        const int jg = tid & 7;
        const int lr = tid >> 3;           // 0..31

        ull acc[2][4];
        {
            ull b0 = pack2(sbv[jg * 8 + 0], sbv[jg * 8 + 1]);
            ull b1 = pack2(sbv[jg * 8 + 2], sbv[jg * 8 + 3]);
            ull b2 = pack2(sbv[jg * 8 + 4], sbv[jg * 8 + 5]);
            ull b3 = pack2(sbv[jg * 8 + 6], sbv[jg * 8 + 7]);
            #pragma unroll
            for (int rr = 0; rr < 2; rr++) {
                acc[rr][0] = b0; acc[rr][1] = b1; acc[rr][2] = b2; acc[rr][3] = b3;
            }
        }
        #pragma unroll 8
        for (int q = 0; q < DQIN; q++) {
            const ulonglong2* wp = (const ulonglong2*)&sW[q * WSS + jg * 8];
            ulonglong2 w01 = wp[0];
            ulonglong2 w23 = wp[1];
            #pragma unroll
            for (int rr = 0; rr < 2; rr++) {
                ull x2 = pack2s(sD[(lr * 2 + rr) * DSS + q]);
                fma2(acc[rr][0], x2, w01.x);
                fma2(acc[rr][1], x2, w01.y);
                fma2(acc[rr][2], x2, w23.x);
                fma2(acc[rr][3], x2, w23.y);
            }
        }
        // convert to tf32, store
        #pragma unroll
        for (int rr = 0; rr < 2; rr++) {
            int l = lr * 2 + rr;
            float4 o0, o1;
            float2 p;
            p = *(float2*)&acc[rr][0]; o0.x = __uint_as_float(to_tf32(p.x)); o0.y = __uint_as_float(to_tf32(p.y));
            p = *(float2*)&acc[rr][1]; o0.z = __uint_as_float(to_tf32(p.x)); o0.w = __uint_as_float(to_tf32(p.y));
            p = *(float2*)&acc[rr][2]; o1.x = __uint_as_float(to_tf32(p.x)); o1.y = __uint_as_float(to_tf32(p.y));
            p = *(float2*)&acc[rr][3]; o1.z = __uint_as_float(to_tf32(p.x)); o1.w = __uint_as_float(to_tf32(p.y));
            float4* dst = (float4*)(g_V + ((size_t)mn << 17) + ((size_t)(l0 + l) << 6) + jg * 8);
            dst[0] = o0; dst[1] = o1;
        }
        if (tid < 64)
            g_x[((size_t)mn << 11) + l0 + tid] = sD[tid * DSS + 33];
        return;
    }

    // ---------------- query role: 128 queries ----------------
    __shared__ float tls[LL];                 // 8 KB timeline
    __shared__ float swa[DQIN], swb[DQIN];
    __shared__ float sconst[3];               // ca, cb, invtau
    __shared__ unsigned char s_flag[128];
    __shared__ float s_red[8];

    const float* Wk = (m == 0 ? Wk1 : (m == 1 ? Wk2 : Wk3));
    const float* bk = (m == 0 ? bk1 : (m == 1 ? bk2 : bk3));
    const float* lt = (m == 0 ? lt1 : (m == 1 ? lt2 : lt3));
    const float* tl = (m == 0 ? t1 : (m == 1 ? t2 : t3)) + (size_t)n * LL;

    const int qb  = blockIdx.x - VBLOCKS;     // 0..QBLOCKS-1
    const int t   = qb * 128 + tid;           // valid for tid < 128
    const int idx = mn * TT + t;

    for (int i = tid; i < LL; i += 256) tls[i] = tl[i];
    if (tid < DQIN) {
        int d = tid;
        float sa = Wq[d * 64 + 0];
        float sb = 0.f;
        #pragma unroll 1
        for (int j = 1; j < 64; j++) {
            float w = Wq[d * 64 + j];
            sa -= w * bk[j - 1];
            sb -= w * Wk[j - 1];
        }
        swa[d] = sa;
        swb[d] = sb;
        if (d == 0) {
            sconst[0] = -bk[63];
            sconst[1] = -Wk[63];
            sconst[2] = __expf(-lt[0]);
        }
    }
    __syncthreads();

    if (tid < 128) {
        const float* rd = ref_data + (size_t)(n * TT + t) * DQIN;
        float a = sconst[0], b = sconst[1];
        #pragma unroll
        for (int d = 0; d < DQIN; d++) {
            float v = rd[d];
            a = fmaf(v, swa[d], a);
            b = fmaf(v, swb[d], b);
        }
        g_alpha[idx] = a;
        g_beta[idx]  = b;

        float rt = ref_t[n * TT + t];
        int lo = 0, hi = LL;
        while (lo < hi) {
            int mid = (lo + hi) >> 1;
            if (tls[mid] <= rt) lo = mid + 1; else hi = mid;
        }
        g_cut[idx] = lo;
        g_M[idx]   = 0.f;
        s_flag[tid] = (lo == LL) ? 1 : 0;
    }
    __syncthreads();

    // cooperative min-z^2 scan for flagged rows (rare) — x read from raw data
    const float invtau = sconst[2];
    for (int tt = 0; tt < 128; tt++) {
        if (!s_flag[tt]) continue;                 // uniform (smem) branch
        int ridx = mn * TT + qb * 128 + tt;
        float aa = g_alpha[ridx], bb = g_beta[ridx];
        float mnv = 3.4e38f;
        #pragma unroll
        for (int j = 0; j < LL / 256; j++) {
            float x = dsrc[(size_t)(n * LL + tid + j * 256) * DF + 33];
            float z = fmaf(bb, x, aa);
            mnv = fminf(mnv, z * z);
        }
        #pragma unroll
        for (int o = 16; o > 0; o >>= 1)
            mnv = fminf(mnv, __shfl_xor_sync(0xffffffffu, mnv, o));
        if ((tid & 31) == 0) s_red[tid >> 5] = mnv;
        __syncthreads();
        if (tid == 0) {
            float mm = s_red[0];
            #pragma unroll
            for (int i = 1; i < 8; i++) mm = fminf(mm, s_red[i]);
            g_M[ridx] = -mm * invtau;
        }
        __syncthreads();
    }
}

// ---------------------------------------------------------------------------
// attn: warp-level tf32 mma.sync flash attention, split-K (KSPLIT=4).
// Block: 64 queries (4 warps x 16), 128 threads, key chunk of 512.
// ---------------------------------------------------------------------------
__global__ __launch_bounds__(128)
void attn(const float* __restrict__ lt1, const float* __restrict__ lt2,
          const float* __restrict__ lt3)
{
    __shared__ alignas(16) float Vs[KT * VSS];   // 18 KB padded V tile [k][d]
    __shared__ float xs[KT];
    __shared__ int   s_red[4];

    const int bx   = blockIdx.x;
    const int csp  = bx & (KSPLIT - 1);
    const int tile = bx >> 2;            // 0..31
    const int n    = blockIdx.y;
    const int m    = blockIdx.z;
    const int tid  = threadIdx.x;
    const int w    = tid >> 5;
    const int lane = tid & 31;
    const int gid  = lane >> 2;          // groupID: q row
    const int tig  = lane & 3;           // thread-in-group: k col

    const int rowbase = (m * NB + n) * TT;
    const int t0      = tile * TQ;
    const int cstart  = csp * CHUNK;
    const int cend    = cstart + CHUNK;

    const float* lt = (m == 0 ? lt1 : (m == 1 ? lt2 : lt3));
    const float c1 = -__expf(-lt[0]) * LOG2E;

    const int r0 = rowbase + t0 + w * 16 + gid;
    const int r1 = r0 + 8;
    const float aq0 = g_alpha[r0], bq0 = g_beta[r0], c20 = -g_M[r0] * LOG2E;
    const float aq1 = g_alpha[r1], bq1 = g_beta[r1], c21 = -g_M[r1] * LOG2E;
    const int lim0 = min(g_cut[r0], cend);
    const int lim1 = min(g_cut[r1], cend);

    const int wbend = __reduce_max_sync(0xffffffffu, max(lim0, lim1));
    if (lane == 0) s_red[w] = wbend;
    __syncthreads();
    const int bbend = max(max(s_red[0], s_red[1]), max(s_red[2], s_red[3]));

    const float* __restrict__ xg = g_x + (size_t)(m * NB + n) * LL;
    const float4* __restrict__ Vg4 = (const float4*)(g_V + ((size_t)(m * NB + n) * LL << 6));

    float acc[8][4];
    #pragma unroll
    for (int nt = 0; nt < 8; nt++)
        #pragma unroll
        for (int i = 0; i < 4; i++) acc[nt][i] = 0.f;
    float den0 = 0.f, den1 = 0.f;

    for (int base = cstart; base < bbend; base += KT) {
        __syncthreads();
        // stage V tile [64 k][64 d] into padded smem + x tile
        #pragma unroll
        for (int i = 0; i < 8; i++) {
            int e = tid + i * 128;
            int k = e >> 4, j = e & 15;
            *(float4*)&Vs[k * VSS + j * 4] = Vg4[((size_t)(base + k) << 4) + j];
        }
        if (tid < KT) xs[tid] = xg[base + tid];
        __syncthreads();

        if (base >= wbend) continue;

        #pragma unroll
        for (int kb = 0; kb < KT; kb += 8) {
            if (base + kb >= wbend) break;
            const int k0 = kb + tig, k1 = k0 + 4;
            const int kg0 = base + k0, kg1 = base + k1;
            const float x0 = xs[k0], x1 = xs[k1];

            float z, e0f, e1f, e2f, e3f;
            z = fmaf(bq0, x0, aq0); e0f = ex2(fmaf(z * z, c1, c20));
            z = fmaf(bq1, x0, aq1); e1f = ex2(fmaf(z * z, c1, c21));
            z = fmaf(bq0, x1, aq0); e2f = ex2(fmaf(z * z, c1, c20));
            z = fmaf(bq1, x1, aq1); e3f = ex2(fmaf(z * z, c1, c21));
            e0f = (kg0 < lim0) ? e0f : 0.f;
            e1f = (kg0 < lim1) ? e1f : 0.f;
            e2f = (kg1 < lim0) ? e2f : 0.f;
            e3f = (kg1 < lim1) ? e3f : 0.f;
            const uint32_t a0 = to_tf32(e0f), a1 = to_tf32(e1f);
            const uint32_t a2 = to_tf32(e2f), a3 = to_tf32(e3f);
            den0 += __uint_as_float(a0) + __uint_as_float(a2);
            den1 += __uint_as_float(a1) + __uint_as_float(a3);

            const uint32_t* vr0 = (const uint32_t*)&Vs[k0 * VSS + gid];
            const uint32_t* vr1 = (const uint32_t*)&Vs[k1 * VSS + gid];
            #pragma unroll
            for (int nt = 0; nt < 8; nt++)
                mma8(acc[nt], a0, a1, a2, a3, vr0[nt * 8], vr1[nt * 8]);
        }
    }

    // denominator: reduce over the 4 k-lanes of each q row
    den0 += __shfl_xor_sync(0xffffffffu, den0, 1);
    den0 += __shfl_xor_sync(0xffffffffu, den0, 2);
    den1 += __shfl_xor_sync(0xffffffffu, den1, 1);
    den1 += __shfl_xor_sync(0xffffffffu, den1, 2);
    if (tig == 0) {
        g_pden[csp * ROWS + r0] = den0;
        g_pden[csp * ROWS + r1] = den1;
    }

    // numerator partials: thread owns cols {2*tig, 2*tig+1} of each n-tile
    float* p0 = g_part + (((size_t)csp * ROWS + r0) << 6);
    float* p1 = g_part + (((size_t)csp * ROWS + r1) << 6);
    #pragma unroll
    for (int nt = 0; nt < 8; nt++) {
        *(float2*)(p0 + nt * 8 + 2 * tig) = make_float2(acc[nt][0], acc[nt][1]);
        *(float2*)(p1 + nt * 8 + 2 * tig) = make_float2(acc[nt][2], acc[nt][3]);
    }
}

// ---------------------------------------------------------------------------
// combine: out = (sum_c part) / (sum_c pden + (LL - cut))
// ---------------------------------------------------------------------------
__global__ void combine(float* __restrict__ out)
{
    int idx = blockIdx.x * blockDim.x + threadIdx.x;   // ROWS * 16 float4s
    if (idx >= ROWS * 16) return;
    int row = idx >> 4;
    int f   = idx & 15;

    float4 s = make_float4(0.f, 0.f, 0.f, 0.f);
    float den = (float)(LL - g_cut[row]);
    #pragma unroll
    for (int c = 0; c < KSPLIT; c++) {
        const float4* p = (const float4*)(g_part + (((size_t)c * ROWS + row) << 6));
        float4 v = p[f];
        s.x += v.x; s.y += v.y; s.z += v.z; s.w += v.w;
        den += g_pden[c * ROWS + row];
    }
    float inv = 1.f / den;
    ((float4*)out)[idx] = make_float4(s.x * inv, s.y * inv, s.z * inv, s.w * inv);
}

// ---------------------------------------------------------------------------
extern "C" void kernel_launch(void* const* d_in, const int* in_sizes, int n_in,
                              void* d_out, int out_size)
{
    const float* ref_data = (const float*)d_in[0];
    const float* ref_t    = (const float*)d_in[1];
    const float* m1_data  = (const float*)d_in[2];
    const float* m1_t     = (const float*)d_in[3];
    const float* m2_data  = (const float*)d_in[4];
    const float* m2_t     = (const float*)d_in[5];
    const float* m3_data  = (const float*)d_in[6];
    const float* m3_t     = (const float*)d_in[7];
    const float* Wq       = (const float*)d_in[8];
    const float* Wk1      = (const float*)d_in[9];
    const float* bk1      = (const float*)d_in[10];
    const float* Wv1      = (const float*)d_in[11];
    const float* bv1      = (const float*)d_in[12];
    const float* lt1      = (const float*)d_in[13];
    const float* Wk2      = (const float*)d_in[14];
    const float* bk2      = (const float*)d_in[15];
    const float* Wv2      = (const float*)d_in[16];
    const float* bv2      = (const float*)d_in[17];
    const float* lt2      = (const float*)d_in[18];
    const float* Wk3      = (const float*)d_in[19];
    const float* bk3      = (const float*)d_in[20];
    const float* Wv3      = (const float*)d_in[21];
    const float* bv3      = (const float*)d_in[22];
    const float* lt3      = (const float*)d_in[23];

    prep<<<dim3(VBLOCKS + QBLOCKS, NB, 3), 256>>>(
        ref_data, ref_t, m1_data, m1_t, m2_data, m2_t, m3_data, m3_t, Wq,
        Wk1, bk1, Wv1, bv1, lt1,
        Wk2, bk2, Wv2, bv2, lt2,
        Wk3, bk3, Wv3, bv3, lt3);
    attn<<<dim3((TT / TQ) * KSPLIT, NB, 3), 128>>>(lt1, lt2, lt3);
    combine<<<(ROWS * 16 + 255) / 256, 256>>>((float*)d_out);
}

// round 14
// speedup vs baseline: 6.6157x; 1.0620x over previous
#include <cuda_runtime.h>
#include <cuda_bf16.h>
#include <cstdint>

#define NB   4
#define TT   2048
#define LL   2048
#define DV   64
#define DQIN 32
#define DF   34
#define ROWS (3 * NB * TT)      // 24576
#define KSPLIT 4
#define CHUNK  (LL / KSPLIT)    // 512
#define KT   64                 // keys staged per smem tile
#define TQ   64                 // queries per block (4 warps x 16)
#define VSS  72                 // padded Vs row stride (floats) -> conflict-free B frags
#define LOG2E 1.4426950408889634f

#define VBLOCKS 32              // V-GEMM blocks per (m,n): 64 rows each
#define QBLOCKS 16              // query blocks per (m,n): 128 queries each

// Scratch (device globals; no allocation allowed)
__device__ float g_V[3 * NB * LL * DV];          // 6 MB  tf32 V rows [mn][l][d]
__device__ float g_x[3 * NB * LL];
__device__ float g_alpha[ROWS];
__device__ float g_beta[ROWS];
__device__ int   g_cut[ROWS];
__device__ float g_M[ROWS];
__device__ float g_part[(size_t)KSPLIT * ROWS * DV];  // 25.2 MB
__device__ float g_pden[KSPLIT * ROWS];

typedef unsigned long long ull;

__device__ __forceinline__ float ex2(float x) {
    float r; asm("ex2.approx.f32 %0, %1;" : "=f"(r) : "f"(x)); return r;
}
__device__ __forceinline__ uint32_t to_tf32(float x) {
    uint32_t u; asm("cvt.rna.tf32.f32 %0, %1;" : "=r"(u) : "f"(x)); return u;
}
__device__ __forceinline__ void fma2(ull& d, ull a, ull b) {
    asm("fma.rn.f32x2 %0, %1, %2, %0;" : "+l"(d) : "l"(a), "l"(b));
}
__device__ __forceinline__ ull pack2s(float x) {
    ull r; asm("mov.b64 %0, {%1, %1};" : "=l"(r) : "f"(x)); return r;
}
__device__ __forceinline__ ull pack2(float x, float y) {
    ull r; asm("mov.b64 %0, {%1, %2};" : "=l"(r) : "f"(x), "f"(y)); return r;
}
// m16n8k8 tf32 MMA: D += A(16x8) * B(8x8)
__device__ __forceinline__ void mma8(float* d, uint32_t a0, uint32_t a1, uint32_t a2, uint32_t a3,
                                     uint32_t b0, uint32_t b1) {
    asm volatile(
        "mma.sync.aligned.m16n8k8.row.col.f32.tf32.tf32.f32 "
        "{%0,%1,%2,%3}, {%4,%5,%6,%7}, {%8,%9}, {%0,%1,%2,%3};"
        : "+f"(d[0]), "+f"(d[1]), "+f"(d[2]), "+f"(d[3])
        : "r"(a0), "r"(a1), "r"(a2), "r"(a3), "r"(b0), "r"(b1));
}

#define DSS 38   // padded smem data row stride (floats)
#define WSS 72   // padded smem Wv row stride

// ---------------------------------------------------------------------------
// prep (fused): grid (VBLOCKS+QBLOCKS, NB, 3), 256 threads.
//  blockIdx.x < VBLOCKS : V-GEMM role — smem-staged block GEMM, 64 rows.
//  else: query role — 128 queries: PARALLEL K-path weight collapse (staged
//     Wq/bk/Wk in smem, 256-thread partial sums + 2-stage reduce), then
//     alpha/beta, mask cutoff (smem binary search), softmax shift M.
// ---------------------------------------------------------------------------
__global__ __launch_bounds__(256)
void prep(const float* __restrict__ ref_data, const float* __restrict__ ref_t,
          const float* __restrict__ d1, const float* __restrict__ t1,
          const float* __restrict__ d2, const float* __restrict__ t2,
          const float* __restrict__ d3, const float* __restrict__ t3,
          const float* __restrict__ Wq,
          const float* __restrict__ Wk1, const float* __restrict__ bk1,
          const float* __restrict__ Wv1, const float* __restrict__ bv1, const float* __restrict__ lt1,
          const float* __restrict__ Wk2, const float* __restrict__ bk2,
          const float* __restrict__ Wv2, const float* __restrict__ bv2, const float* __restrict__ lt2,
          const float* __restrict__ Wk3, const float* __restrict__ bk3,
          const float* __restrict__ Wv3, const float* __restrict__ bv3, const float* __restrict__ lt3)
{
    const int m   = blockIdx.z;
    const int n   = blockIdx.y;
    const int tid = threadIdx.x;
    const int mn  = m * NB + n;

    const float* dsrc = (m == 0 ? d1 : (m == 1 ? d2 : d3));

    if (blockIdx.x < VBLOCKS) {
        // ---------------- V-GEMM role: 64 rows ----------------
        __shared__ alignas(16) float sD[64 * DSS];    // 9.5 KB staged data rows
        __shared__ alignas(16) float sW[DQIN * WSS];  // 9 KB  padded Wv
        __shared__ alignas(16) float sbv[DV];

        const float* Wv = (m == 0 ? Wv1 : (m == 1 ? Wv2 : Wv3));
        const float* bv = (m == 0 ? bv1 : (m == 1 ? bv2 : bv3));
        const int l0 = blockIdx.x * 64;

        for (int i = tid; i < DQIN * DV; i += 256)
            sW[(i >> 6) * WSS + (i & 63)] = Wv[i];
        if (tid < DV) sbv[tid] = bv[tid];

        // stage 64 rows x 34 floats, coalesced float2 (row pitch 136 B, 8B-aligned)
        const float2* src = (const float2*)(dsrc + (size_t)(n * LL + l0) * DF);
        #pragma unroll
        for (int i = tid; i < 64 * (DF / 2); i += 256) {
            int r = i / (DF / 2), c = i - r * (DF / 2);
            *(float2*)&sD[r * DSS + c * 2] = src[i];
        }
        __syncthreads();

        // thread = rows {lr*2, lr*2+1} x dims {jg*8 .. jg*8+7}
        const int jg = tid & 7;
        const int lr = tid >> 3;           // 0..31

        ull acc[2][4];
        {
            ull b0 = pack2(sbv[jg * 8 + 0], sbv[jg * 8 + 1]);
            ull b1 = pack2(sbv[jg * 8 + 2], sbv[jg * 8 + 3]);
            ull b2 = pack2(sbv[jg * 8 + 4], sbv[jg * 8 + 5]);
            ull b3 = pack2(sbv[jg * 8 + 6], sbv[jg * 8 + 7]);
            #pragma unroll
            for (int rr = 0; rr < 2; rr++) {
                acc[rr][0] = b0; acc[rr][1] = b1; acc[rr][2] = b2; acc[rr][3] = b3;
            }
        }
        #pragma unroll 8
        for (int q = 0; q < DQIN; q++) {
            const ulonglong2* wp = (const ulonglong2*)&sW[q * WSS + jg * 8];
            ulonglong2 w01 = wp[0];
            ulonglong2 w23 = wp[1];
            #pragma unroll
            for (int rr = 0; rr < 2; rr++) {
                ull x2 = pack2s(sD[(lr * 2 + rr) * DSS + q]);
                fma2(acc[rr][0], x2, w01.x);
                fma2(acc[rr][1], x2, w01.y);
                fma2(acc[rr][2], x2, w23.x);
                fma2(acc[rr][3], x2, w23.y);
            }
        }
        // convert to tf32, store
        #pragma unroll
        for (int rr = 0; rr < 2; rr++) {
            int l = lr * 2 + rr;
            float4 o0, o1;
            float2 p;
            p = *(float2*)&acc[rr][0]; o0.x = __uint_as_float(to_tf32(p.x)); o0.y = __uint_as_float(to_tf32(p.y));
            p = *(float2*)&acc[rr][1]; o0.z = __uint_as_float(to_tf32(p.x)); o0.w = __uint_as_float(to_tf32(p.y));
            p = *(float2*)&acc[rr][2]; o1.x = __uint_as_float(to_tf32(p.x)); o1.y = __uint_as_float(to_tf32(p.y));
            p = *(float2*)&acc[rr][3]; o1.z = __uint_as_float(to_tf32(p.x)); o1.w = __uint_as_float(to_tf32(p.y));
            float4* dst = (float4*)(g_V + ((size_t)mn << 17) + ((size_t)(l0 + l) << 6) + jg * 8);
            dst[0] = o0; dst[1] = o1;
        }
        if (tid < 64)
            g_x[((size_t)mn << 11) + l0 + tid] = sD[tid * DSS + 33];
        return;
    }

    // ---------------- query role: 128 queries ----------------
    __shared__ float tls[LL];                 // 8 KB timeline
    __shared__ float sWq[DQIN * 64];          // 8 KB staged Wq
    __shared__ float sbk[64], sWkk[64];
    __shared__ float spart[2][DQIN][8];       // collapse partials
    __shared__ float swa[DQIN], swb[DQIN];
    __shared__ float sconst[3];               // ca, cb, invtau
    __shared__ unsigned char s_flag[128];
    __shared__ float s_red[8];

    const float* Wk = (m == 0 ? Wk1 : (m == 1 ? Wk2 : Wk3));
    const float* bk = (m == 0 ? bk1 : (m == 1 ? bk2 : bk3));
    const float* lt = (m == 0 ? lt1 : (m == 1 ? lt2 : lt3));
    const float* tl = (m == 0 ? t1 : (m == 1 ? t2 : t3)) + (size_t)n * LL;

    const int qb  = blockIdx.x - VBLOCKS;     // 0..QBLOCKS-1
    const int t   = qb * 128 + tid;           // valid for tid < 128
    const int idx = mn * TT + t;

    // stage everything coalesced
    for (int i = tid; i < LL; i += 256) tls[i] = tl[i];
    for (int i = tid; i < DQIN * 64; i += 256) sWq[i] = Wq[i];
    if (tid < 64) { sbk[tid] = bk[tid]; sWkk[tid] = Wk[tid]; }
    if (tid == 0) {
        sconst[0] = -bk[63];
        sconst[1] = -Wk[63];
        sconst[2] = __expf(-lt[0]);
    }
    __syncthreads();

    // parallel collapse: thread = (d = tid>>3, part p = tid&7), 8 j's each
    {
        const int d = tid >> 3;
        const int p = tid & 7;
        float sa = 0.f, sb = 0.f;
        #pragma unroll
        for (int jj = 0; jj < 8; jj++) {
            int j = p * 8 + jj;
            if (j >= 1) {              // j in 1..63
                float w = sWq[d * 64 + j];
                sa -= w * sbk[j - 1];
                sb -= w * sWkk[j - 1];
            }
        }
        if (p == 0) sa += sWq[d * 64];
        spart[0][d][p] = sa;
        spart[1][d][p] = sb;
    }
    __syncthreads();
    if (tid < 64) {
        const int d = tid & 31, which = tid >> 5;
        float s = 0.f;
        #pragma unroll
        for (int p = 0; p < 8; p++) s += spart[which][d][p];
        if (which == 0) swa[d] = s; else swb[d] = s;
    }
    __syncthreads();

    if (tid < 128) {
        const float* rd = ref_data + (size_t)(n * TT + t) * DQIN;
        float a = sconst[0], b = sconst[1];
        #pragma unroll
        for (int d = 0; d < DQIN; d++) {
            float v = rd[d];
            a = fmaf(v, swa[d], a);
            b = fmaf(v, swb[d], b);
        }
        g_alpha[idx] = a;
        g_beta[idx]  = b;

        float rt = ref_t[n * TT + t];
        int lo = 0, hi = LL;
        while (lo < hi) {
            int mid = (lo + hi) >> 1;
            if (tls[mid] <= rt) lo = mid + 1; else hi = mid;
        }
        g_cut[idx] = lo;
        g_M[idx]   = 0.f;
        s_flag[tid] = (lo == LL) ? 1 : 0;
    }
    __syncthreads();

    // cooperative min-z^2 scan for flagged rows (rare) — x read from raw data
    const float invtau = sconst[2];
    for (int tt = 0; tt < 128; tt++) {
        if (!s_flag[tt]) continue;                 // uniform (smem) branch
        int ridx = mn * TT + qb * 128 + tt;
        float aa = g_alpha[ridx], bb = g_beta[ridx];
        float mnv = 3.4e38f;
        #pragma unroll
        for (int j = 0; j < LL / 256; j++) {
            float x = dsrc[(size_t)(n * LL + tid + j * 256) * DF + 33];
            float z = fmaf(bb, x, aa);
            mnv = fminf(mnv, z * z);
        }
        #pragma unroll
        for (int o = 16; o > 0; o >>= 1)
            mnv = fminf(mnv, __shfl_xor_sync(0xffffffffu, mnv, o));
        if ((tid & 31) == 0) s_red[tid >> 5] = mnv;
        __syncthreads();
        if (tid == 0) {
            float mm = s_red[0];
            #pragma unroll
            for (int i = 1; i < 8; i++) mm = fminf(mm, s_red[i]);
            g_M[ridx] = -mm * invtau;
        }
        __syncthreads();
    }
}

// ---------------------------------------------------------------------------
// attn: warp-level tf32 mma.sync flash attention, split-K (KSPLIT=4).
// Block: 64 queries (4 warps x 16), 128 threads, key chunk of 512.
// ---------------------------------------------------------------------------
__global__ __launch_bounds__(128)
void attn(const float* __restrict__ lt1, const float* __restrict__ lt2,
          const float* __restrict__ lt3)
{
    __shared__ alignas(16) float Vs[KT * VSS];   // 18 KB padded V tile [k][d]
    __shared__ float xs[KT];
    __shared__ int   s_red[4];

    const int bx   = blockIdx.x;
    const int csp  = bx & (KSPLIT - 1);
    const int tile = bx >> 2;            // 0..31
    const int n    = blockIdx.y;
    const int m    = blockIdx.z;
    const int tid  = threadIdx.x;
    const int w    = tid >> 5;
    const int lane = tid & 31;
    const int gid  = lane >> 2;          // groupID: q row
    const int tig  = lane & 3;           // thread-in-group: k col

    const int rowbase = (m * NB + n) * TT;
    const int t0      = tile * TQ;
    const int cstart  = csp * CHUNK;
    const int cend    = cstart + CHUNK;

    const float* lt = (m == 0 ? lt1 : (m == 1 ? lt2 : lt3));
    const float c1 = -__expf(-lt[0]) * LOG2E;

    const int r0 = rowbase + t0 + w * 16 + gid;
    const int r1 = r0 + 8;
    const float aq0 = g_alpha[r0], bq0 = g_beta[r0], c20 = -g_M[r0] * LOG2E;
    const float aq1 = g_alpha[r1], bq1 = g_beta[r1], c21 = -g_M[r1] * LOG2E;
    const int lim0 = min(g_cut[r0], cend);
    const int lim1 = min(g_cut[r1], cend);

    const int wbend = __reduce_max_sync(0xffffffffu, max(lim0, lim1));
    if (lane == 0) s_red[w] = wbend;
    __syncthreads();
    const int bbend = max(max(s_red[0], s_red[1]), max(s_red[2], s_red[3]));

    const float* __restrict__ xg = g_x + (size_t)(m * NB + n) * LL;
    const float4* __restrict__ Vg4 = (const float4*)(g_V + ((size_t)(m * NB + n) * LL << 6));

    float acc[8][4];
    #pragma unroll
    for (int nt = 0; nt < 8; nt++)
        #pragma unroll
        for (int i = 0; i < 4; i++) acc[nt][i] = 0.f;
    float den0 = 0.f, den1 = 0.f;

    for (int base = cstart; base < bbend; base += KT) {
        __syncthreads();
        // stage V tile [64 k][64 d] into padded smem + x tile
        #pragma unroll
        for (int i = 0; i < 8; i++) {
            int e = tid + i * 128;
            int k = e >> 4, j = e & 15;
            *(float4*)&Vs[k * VSS + j * 4] = Vg4[((size_t)(base + k) << 4) + j];
        }
        if (tid < KT) xs[tid] = xg[base + tid];
        __syncthreads();

        if (base >= wbend) continue;

        #pragma unroll
        for (int kb = 0; kb < KT; kb += 8) {
            if (base + kb >= wbend) break;
            const int k0 = kb + tig, k1 = k0 + 4;
            const int kg0 = base + k0, kg1 = base + k1;
            const float x0 = xs[k0], x1 = xs[k1];

            float z, e0f, e1f, e2f, e3f;
            z = fmaf(bq0, x0, aq0); e0f = ex2(fmaf(z * z, c1, c20));
            z = fmaf(bq1, x0, aq1); e1f = ex2(fmaf(z * z, c1, c21));
            z = fmaf(bq0, x1, aq0); e2f = ex2(fmaf(z * z, c1, c20));
            z = fmaf(bq1, x1, aq1); e3f = ex2(fmaf(z * z, c1, c21));
            e0f = (kg0 < lim0) ? e0f : 0.f;
            e1f = (kg0 < lim1) ? e1f : 0.f;
            e2f = (kg1 < lim0) ? e2f : 0.f;
            e3f = (kg1 < lim1) ? e3f : 0.f;
            const uint32_t a0 = to_tf32(e0f), a1 = to_tf32(e1f);
            const uint32_t a2 = to_tf32(e2f), a3 = to_tf32(e3f);
            den0 += __uint_as_float(a0) + __uint_as_float(a2);
            den1 += __uint_as_float(a1) + __uint_as_float(a3);

            const uint32_t* vr0 = (const uint32_t*)&Vs[k0 * VSS + gid];
            const uint32_t* vr1 = (const uint32_t*)&Vs[k1 * VSS + gid];
            #pragma unroll
            for (int nt = 0; nt < 8; nt++)
                mma8(acc[nt], a0, a1, a2, a3, vr0[nt * 8], vr1[nt * 8]);
        }
    }

    // denominator: reduce over the 4 k-lanes of each q row
    den0 += __shfl_xor_sync(0xffffffffu, den0, 1);
    den0 += __shfl_xor_sync(0xffffffffu, den0, 2);
    den1 += __shfl_xor_sync(0xffffffffu, den1, 1);
    den1 += __shfl_xor_sync(0xffffffffu, den1, 2);
    if (tig == 0) {
        g_pden[csp * ROWS + r0] = den0;
        g_pden[csp * ROWS + r1] = den1;
    }

    // numerator partials: thread owns cols {2*tig, 2*tig+1} of each n-tile
    float* p0 = g_part + (((size_t)csp * ROWS + r0) << 6);
    float* p1 = g_part + (((size_t)csp * ROWS + r1) << 6);
    #pragma unroll
    for (int nt = 0; nt < 8; nt++) {
        *(float2*)(p0 + nt * 8 + 2 * tig) = make_float2(acc[nt][0], acc[nt][1]);
        *(float2*)(p1 + nt * 8 + 2 * tig) = make_float2(acc[nt][2], acc[nt][3]);
    }
}

// ---------------------------------------------------------------------------
// combine: out = (sum_c part) / (sum_c pden + (LL - cut))
// ---------------------------------------------------------------------------
__global__ void combine(float* __restrict__ out)
{
    int idx = blockIdx.x * blockDim.x + threadIdx.x;   // ROWS * 16 float4s
    if (idx >= ROWS * 16) return;
    int row = idx >> 4;
    int f   = idx & 15;

    float4 s = make_float4(0.f, 0.f, 0.f, 0.f);
    float den = (float)(LL - g_cut[row]);
    #pragma unroll
    for (int c = 0; c < KSPLIT; c++) {
        const float4* p = (const float4*)(g_part + (((size_t)c * ROWS + row) << 6));
        float4 v = p[f];
        s.x += v.x; s.y += v.y; s.z += v.z; s.w += v.w;
        den += g_pden[c * ROWS + row];
    }
    float inv = 1.f / den;
    ((float4*)out)[idx] = make_float4(s.x * inv, s.y * inv, s.z * inv, s.w * inv);
}

// ---------------------------------------------------------------------------
extern "C" void kernel_launch(void* const* d_in, const int* in_sizes, int n_in,
                              void* d_out, int out_size)
{
    const float* ref_data = (const float*)d_in[0];
    const float* ref_t    = (const float*)d_in[1];
    const float* m1_data  = (const float*)d_in[2];
    const float* m1_t     = (const float*)d_in[3];
    const float* m2_data  = (const float*)d_in[4];
    const float* m2_t     = (const float*)d_in[5];
    const float* m3_data  = (const float*)d_in[6];
    const float* m3_t     = (const float*)d_in[7];
    const float* Wq       = (const float*)d_in[8];
    const float* Wk1      = (const float*)d_in[9];
    const float* bk1      = (const float*)d_in[10];
    const float* Wv1      = (const float*)d_in[11];
    const float* bv1      = (const float*)d_in[12];
    const float* lt1      = (const float*)d_in[13];
    const float* Wk2      = (const float*)d_in[14];
    const float* bk2      = (const float*)d_in[15];
    const float* Wv2      = (const float*)d_in[16];
    const float* bv2      = (const float*)d_in[17];
    const float* lt2      = (const float*)d_in[18];
    const float* Wk3      = (const float*)d_in[19];
    const float* bk3      = (const float*)d_in[20];
    const float* Wv3      = (const float*)d_in[21];
    const float* bv3      = (const float*)d_in[22];
    const float* lt3      = (const float*)d_in[23];

    prep<<<dim3(VBLOCKS + QBLOCKS, NB, 3), 256>>>(
        ref_data, ref_t, m1_data, m1_t, m2_data, m2_t, m3_data, m3_t, Wq,
        Wk1, bk1, Wv1, bv1, lt1,
        Wk2, bk2, Wv2, bv2, lt2,
        Wk3, bk3, Wv3, bv3, lt3);
    attn<<<dim3((TT / TQ) * KSPLIT, NB, 3), 128>>>(lt1, lt2, lt3);
    combine<<<(ROWS * 16 + 255) / 256, 256>>>((float*)d_out);
}